// round 12
// baseline (speedup 1.0000x reference)
#include <cuda_runtime.h>
#include <cuda_fp16.h>
#include <cstdint>
#include <cstddef>

// ---------------- problem constants ----------------
#define NA 50000
#define NROW 50000
#define EDG 800000
#define EHALF (EDG / 2)
#define SZ (50000 * 128)        // floats per [N,128] fp32-equivalent slot
#define XQ4 3200000             // float4 count per x array (50000*256/4)

#define GB 391                  // gemm blocks per matrix (128-row tiles)
#define GWB 6250                // gather blocks per relation-set (8 rows/block)

// scratch layout (float units):
#define OFF_AGGH   0ull                           // 3 x [N,128] fp16 (1.5 slots)
#define OFF_FTH    (2ull * SZ)                    // 4 x [N,128] fp16 (2 slots)
#define OFF_XH     (4ull * SZ)                    // 3 x [N,256] fp16 (3 slots)
#define W_OFF      (7ull * SZ)
#define OFF_WH     (W_OFF)                        // 4*256*128 halves = 65536 floats
#define OFF_WCOMB  (OFF_WH + 65536)               // 3*384*128 halves = 73728 floats
#define OFF_UV     (OFF_WCOMB + 73728)            // 512 floats
#define OFF_DEG    (OFF_UV   + 512)
#define OFF_BASE   (OFF_DEG  + 4*50000)
#define OFF_CUR    (OFF_BASE + 4*50004)
#define OFF_EPACK  (((OFF_CUR + 4*50000) + 3) & ~3ull)   // 16B-aligned
#define SCRATCH_TOTAL (OFF_EPACK + 4ull*EDG*2)

__device__ __align__(256) float g_scratch[SCRATCH_TOTAL];

// ---------------- helpers ----------------
__device__ __forceinline__ void ldsm4(unsigned &r0, unsigned &r1, unsigned &r2,
                                      unsigned &r3, unsigned addr) {
    asm volatile("ldmatrix.sync.aligned.m8n8.x4.shared.b16 {%0,%1,%2,%3}, [%4];"
                 : "=r"(r0), "=r"(r1), "=r"(r2), "=r"(r3) : "r"(addr));
}

__device__ __forceinline__ void ldsm4t(unsigned &r0, unsigned &r1, unsigned &r2,
                                       unsigned &r3, unsigned addr) {
    asm volatile("ldmatrix.sync.aligned.m8n8.x4.trans.shared.b16 {%0,%1,%2,%3}, [%4];"
                 : "=r"(r0), "=r"(r1), "=r"(r2), "=r"(r3) : "r"(addr));
}

__device__ __forceinline__ void mma_f16(float c[4], const unsigned a[4],
                                        unsigned b0, unsigned b1) {
    asm volatile(
        "mma.sync.aligned.m16n8k16.row.col.f32.f16.f16.f32 "
        "{%0,%1,%2,%3}, {%4,%5,%6,%7}, {%8,%9}, {%0,%1,%2,%3};"
        : "+f"(c[0]), "+f"(c[1]), "+f"(c[2]), "+f"(c[3])
        : "r"(a[0]), "r"(a[1]), "r"(a[2]), "r"(a[3]), "r"(b0), "r"(b1));
}

__device__ __forceinline__ void cpasync16(void* sdst, const void* gsrc, int nbytes) {
    unsigned s = (unsigned)__cvta_generic_to_shared(sdst);
    asm volatile("cp.async.cg.shared.global [%0], [%1], 16, %2;\n"
                 :: "r"(s), "l"(gsrc), "r"(nbytes));
}

// ================= fp16 GEMM body (K-tiles of 32) =========================
template<int NKT, bool HOUT, bool SPLIT>
__device__ __forceinline__ void gemm_f16_body(
    const __half* __restrict__ A0, int lda0,
    const __half* __restrict__ A1, int lda1,
    const __half* __restrict__ B,                     // [K][128] row-major
    const float* __restrict__ bias,
    __half* __restrict__ Yh, float* __restrict__ Yf, int bx)
{
    __shared__ __half As[2][128][40];    // 32 k + 8 pad
    __shared__ __half Bs[2][32][136];    // [k][n], 128 n + 8 pad

    const int tid  = threadIdx.x;
    const int lane = tid & 31;
    const int w    = tid >> 5;
    const int bm   = bx * 128;

    const int wm = (w >> 2) * 64;
    const int wn = (w & 3) * 32;

    float acc[4][4][4];
    #pragma unroll
    for (int i = 0; i < 4; i++)
        #pragma unroll
        for (int j = 0; j < 4; j++)
            #pragma unroll
            for (int c = 0; c < 4; c++) acc[i][j][c] = 0.f;

    auto stage = [&](int buf, int k0) {
        const __half* asrc; int ld, col;
        if (SPLIT && k0 >= 128) { asrc = A1; ld = lda1; col = k0 - 128; }
        else                    { asrc = A0; ld = lda0; col = k0; }
        #pragma unroll
        for (int i = 0; i < 2; i++) {
            int slot = tid + i * 256;
            int r = slot >> 2, c = (slot & 3) * 8;
            int grow = bm + r;
            const __half* src = asrc + (size_t)(grow < NA ? grow : 0) * ld + col + c;
            cpasync16(&As[buf][r][c], src, grow < NA ? 16 : 0);
        }
        #pragma unroll
        for (int i = 0; i < 2; i++) {
            int slot = tid + i * 256;
            int r = slot >> 4, c = (slot & 15) * 8;
            cpasync16(&Bs[buf][r][c], B + (size_t)(k0 + r) * 128 + c, 16);
        }
        asm volatile("cp.async.commit_group;\n" ::);
    };

    stage(0, 0);

    for (int kt = 0; kt < NKT; kt++) {
        if (kt + 1 < NKT) {
            stage((kt + 1) & 1, (kt + 1) * 32);
            asm volatile("cp.async.wait_group 1;\n" ::);
        } else {
            asm volatile("cp.async.wait_group 0;\n" ::);
        }
        __syncthreads();

        const int buf = kt & 1;
        #pragma unroll
        for (int ks = 0; ks < 2; ks++) {
            const int k16 = ks * 16;
            unsigned a[4][4], b0[4], b1[4];
            #pragma unroll
            for (int mt = 0; mt < 4; mt++) {
                unsigned addr = (unsigned)__cvta_generic_to_shared(
                    &As[buf][wm + mt * 16 + (lane & 15)][k16 + (lane >> 4) * 8]);
                ldsm4(a[mt][0], a[mt][1], a[mt][2], a[mt][3], addr);
            }
            #pragma unroll
            for (int np = 0; np < 2; np++) {
                unsigned addr = (unsigned)__cvta_generic_to_shared(
                    &Bs[buf][k16 + (lane & 15)][wn + np * 16 + (lane >> 4) * 8]);
                ldsm4t(b0[np * 2], b1[np * 2], b0[np * 2 + 1], b1[np * 2 + 1], addr);
            }
            #pragma unroll
            for (int mt = 0; mt < 4; mt++)
                #pragma unroll
                for (int nt = 0; nt < 4; nt++)
                    mma_f16(acc[mt][nt], a[mt], b0[nt], b1[nt]);
        }
        __syncthreads();
    }

    const int g = lane >> 2, tg = lane & 3;
    #pragma unroll
    for (int nt = 0; nt < 4; nt++) {
        int cc = wn + nt * 8 + tg * 2;
        float bx0 = HOUT ? 0.f : bias[cc];
        float bx1 = HOUT ? 0.f : bias[cc + 1];
        #pragma unroll
        for (int mt = 0; mt < 4; mt++) {
            int r = bm + wm + mt * 16 + g;
            if (r < NA) {
                if (HOUT)
                    *(__half2*)(Yh + (size_t)r * 128 + cc) =
                        __floats2half2_rn(acc[mt][nt][0], acc[mt][nt][1]);
                else
                    *(float2*)(Yf + (size_t)r * 128 + cc) =
                        make_float2(acc[mt][nt][0] + bx0, acc[mt][nt][1] + bx1);
            }
            if (r + 8 < NA) {
                if (HOUT)
                    *(__half2*)(Yh + (size_t)(r + 8) * 128 + cc) =
                        __floats2half2_rn(acc[mt][nt][2], acc[mt][nt][3]);
                else
                    *(float2*)(Yf + (size_t)(r + 8) * 128 + cc) =
                        make_float2(acc[mt][nt][2] + bx0, acc[mt][nt][3] + bx1);
            }
        }
    }
}

// ---- proj GEMMs (4) + degree hist in one grid (verbatim from R8) ----
#define GEMMB 1564   // 391*4
#define HISTB 512
__global__ void __launch_bounds__(256, 2) mega_proj_hist(
    const __half* __restrict__ xh, const __half* __restrict__ Wh,
    __half* __restrict__ fth,
    const int* __restrict__ r0, const int* __restrict__ r1,
    const int* __restrict__ r2, const int* __restrict__ r3,
    int* __restrict__ deg)
{
    int bid = blockIdx.x;
    if (bid < GEMMB) {
        int y = bid / 391;
        int bx = bid - y * 391;
        // y0: x_b@W_ab, y1: x_c@W_ac, y2: x_a@W_ba, y3: x_a@W_ca
        const __half* A = (y == 0) ? xh + 1ull * NROW * 256
                        : (y == 1) ? xh + 2ull * NROW * 256
                                   : xh;
        gemm_f16_body<8, true, false>(A, 256, nullptr, 0,
                                      Wh + (size_t)y * 256 * 128, nullptr,
                                      fth + (size_t)y * NROW * 128, nullptr, bx);
    } else {
        int hb = bid - GEMMB;
        for (int i = hb * 256 + threadIdx.x; i < 4 * EDG; i += HISTB * 256) {
            int rel = i / EDG;
            int e   = i - rel * EDG;
            const int* row = (rel == 0) ? r0 : (rel == 1) ? r1 : (rel == 2) ? r2 : r3;
            atomicAdd(&deg[rel * NROW + row[e]], 1);
        }
    }
}

// ---- output GEMM body (selects per-type pointers) ----
__device__ __forceinline__ void gemm_out_body(
    int y, int bx,
    const __half* __restrict__ aggh, const __half* __restrict__ xh,
    const __half* __restrict__ Wcomb,
    const float* __restrict__ ba, const float* __restrict__ bb,
    const float* __restrict__ bc, float* __restrict__ outbase)
{
    const float* bias = (y == 0) ? ba : (y == 1) ? bb : bc;
    gemm_f16_body<12, false, true>(
        aggh + (size_t)y * NROW * 128, 128,
        xh   + (size_t)y * NROW * 256, 256,
        Wcomb + (size_t)y * 384 * 128,
        bias, nullptr, outbase + (size_t)y * NROW * 128, bx);
}

// ================= mega prep kernel (verbatim from R8) ====================
#define CONVB 2048
#define WHB   512
#define WC1B  192
#define FOLDB 384
#define UVB   1
#define ZEROB 782
__global__ void mega_prep(
    const float* __restrict__ xa, const float* __restrict__ xb,
    const float* __restrict__ xc, uint2* __restrict__ xh_u2,
    const float* __restrict__ Wab, const float* __restrict__ Wac,
    const float* __restrict__ Wba, const float* __restrict__ Wca,
    __half* __restrict__ Wh,
    const float* __restrict__ wca_, const float* __restrict__ wcb_,
    const float* __restrict__ wcc_,
    const float* __restrict__ wsa, const float* __restrict__ wsb,
    const float* __restrict__ wsc, __half* __restrict__ Wcomb,
    const float* __restrict__ wq, const float* __restrict__ wk,
    const float* __restrict__ watt, float* __restrict__ uv,
    int* __restrict__ deg)
{
    int bid = blockIdx.x;
    int tid = threadIdx.x;

    if (bid < CONVB) {
        for (int i = bid * 256 + tid; i < 3 * XQ4; i += CONVB * 256) {
            int arr = i / XQ4;
            int off = i - arr * XQ4;
            const float* src = (arr == 0) ? xa : (arr == 1) ? xb : xc;
            float4 v = ((const float4*)src)[off];
            __half2 h0 = __floats2half2_rn(v.x, v.y);
            __half2 h1 = __floats2half2_rn(v.z, v.w);
            uint2 u;
            u.x = *(unsigned*)&h0;
            u.y = *(unsigned*)&h1;
            xh_u2[(size_t)arr * XQ4 + off] = u;
        }
        return;
    }
    bid -= CONVB;
    if (bid < WHB) {
        int rel = bid >> 7, blk = bid & 127;
        const float* W = (rel == 0) ? Wab : (rel == 1) ? Wac : (rel == 2) ? Wba : Wca;
        int idx = blk * 256 + tid;
        Wh[(size_t)rel * 32768 + idx] = __float2half(W[idx]);
        return;
    }
    bid -= WHB;
    if (bid < WC1B) {
        int m = bid / 64, blk = bid - m * 64;
        const float* wc = (m == 0) ? wca_ : (m == 1) ? wcb_ : wcc_;
        int idx = blk * 256 + tid;   // 0..16383
        Wcomb[(size_t)m * 49152 + idx] = __float2half(wc[idx]);
        return;
    }
    bid -= WC1B;
    if (bid < FOLDB) {
        int m = bid >> 7, blk = bid & 127;
        const float* ws = (m == 0) ? wsa : (m == 1) ? wsb : wsc;
        const float* wc = ((m == 0) ? wca_ : (m == 1) ? wcb_ : wcc_) + 128 * 128;
        int idx = blk * 256 + tid;   // 0..32767
        int k = idx >> 7, n = idx & 127;
        float s = 0.f;
        #pragma unroll 8
        for (int j = 0; j < 128; j++) s += ws[k * 128 + j] * wc[j * 128 + n];
        Wcomb[(size_t)m * 49152 + (128 + k) * 128 + n] = __float2half(s);
        return;
    }
    bid -= FOLDB;
    if (bid < UVB) {
        if (tid < 128) {
            float s = 0.f;
            #pragma unroll
            for (int j = 0; j < 64; j++) s += wk[tid * 64 + j] * watt[j];
            uv[tid] = s;
        } else {
            int i = tid - 128;
            float s = 0.f;
            #pragma unroll
            for (int j = 0; j < 64; j++) s += wq[i * 64 + j] * watt[64 + j];
            uv[128 + i] = s;
        }
        __syncthreads();
        {
            const float* v = uv + 128;
            float s = 0.f;
            #pragma unroll 8
            for (int j = 0; j < 128; j++) s += wsa[tid * 128 + j] * v[j];
            uv[256 + tid] = s;
        }
        return;
    }
    bid -= UVB;
    {
        int i = bid * 256 + tid;
        if (i < 4 * NROW) deg[i] = 0;
    }
}

// ================= CSR: scan + scatter (verbatim from R8) =================
__global__ void __launch_bounds__(1024) exscan4(const int* __restrict__ degbase,
                                                int* __restrict__ basebase,
                                                int* __restrict__ curbase)
{
    const int* deg = degbase + blockIdx.x * NROW;
    int* base = basebase + blockIdx.x * (NROW + 1);
    int* cur  = curbase  + blockIdx.x * NROW;

    __shared__ int wsum[32];
    __shared__ int carry;
    int tid = threadIdx.x, lane = tid & 31, wid = tid >> 5;
    if (tid == 0) carry = 0;
    __syncthreads();

    for (int start = 0; start < NROW; start += 1024) {
        int i = start + tid;
        int v = (i < NROW) ? deg[i] : 0;
        int x = v;
        #pragma unroll
        for (int off = 1; off < 32; off <<= 1) {
            int t = __shfl_up_sync(0xffffffffu, x, off);
            if (lane >= off) x += t;
        }
        if (lane == 31) wsum[wid] = x;
        __syncthreads();
        if (wid == 0) {
            int s = wsum[lane];
            #pragma unroll
            for (int off = 1; off < 32; off <<= 1) {
                int t = __shfl_up_sync(0xffffffffu, s, off);
                if (lane >= off) s += t;
            }
            wsum[lane] = s;
        }
        __syncthreads();
        int incl = x + (wid ? wsum[wid - 1] : 0) + carry;
        if (i < NROW) { base[i] = incl - v; cur[i] = incl - v; }
        __syncthreads();
        if (tid == 0) carry += wsum[31];
        __syncthreads();
    }
    if (threadIdx.x == 0) base[NROW] = carry;
}

#define SCB 1563
__global__ void scatter4(const int* __restrict__ r0, const int* __restrict__ c0, const float* __restrict__ v0,
                         const int* __restrict__ r1, const int* __restrict__ c1, const float* __restrict__ v1,
                         const int* __restrict__ r2, const int* __restrict__ c2, const float* __restrict__ v2,
                         const int* __restrict__ r3, const int* __restrict__ c3, const float* __restrict__ v3,
                         int* __restrict__ curbase, int2* __restrict__ epackbase)
{
    const int* row; const int* col; const float* val;
    switch (blockIdx.y) {
        case 0: row = r0; col = c0; val = v0; break;
        case 1: row = r1; col = c1; val = v1; break;
        case 2: row = r2; col = c2; val = v2; break;
        default: row = r3; col = c3; val = v3; break;
    }
    int* cur = curbase + blockIdx.y * NROW;
    int2* ep = epackbase + (size_t)blockIdx.y * EDG;
    int i = blockIdx.x * blockDim.x + threadIdx.x;
    if (i >= EHALF) return;
    int ra = row[i],         rb = row[i + EHALF];
    int ca = col[i],         cb = col[i + EHALF];
    float va = val[i],       vb = val[i + EHALF];
    int pa = atomicAdd(&cur[ra], 1);
    int pb = atomicAdd(&cur[rb], 1);
    ep[pa] = make_int2(ca, __float_as_int(va));
    ep[pb] = make_int2(cb, __float_as_int(vb));
}

// ================= gather primitives (verbatim from R8) ===================
__device__ __forceinline__ void edge_accum(float4& acc, float v,
                                           const __half* __restrict__ ft,
                                           int c, int lane)
{
    uint2 u = ((const uint2*)(ft + (size_t)c * 128))[lane];
    float2 l0 = __half22float2(*(__half2*)&u.x);
    float2 l1 = __half22float2(*(__half2*)&u.y);
    acc.x += v * l0.x; acc.y += v * l0.y;
    acc.z += v * l1.x; acc.w += v * l1.y;
}

__device__ __forceinline__ float4 gather_row(
    const int2* __restrict__ ep, const int* __restrict__ base,
    int r, const __half* __restrict__ ft, int lane)
{
    int s = base[r], e = base[r + 1];
    float4 acc = make_float4(0.f, 0.f, 0.f, 0.f);
    int j = s;
    for (; j + 3 < e; j += 4) {
        int2 p0 = ep[j],     p1 = ep[j + 1];
        int2 p2 = ep[j + 2], p3 = ep[j + 3];
        edge_accum(acc, __int_as_float(p0.y), ft, p0.x, lane);
        edge_accum(acc, __int_as_float(p1.y), ft, p1.x, lane);
        edge_accum(acc, __int_as_float(p2.y), ft, p2.x, lane);
        edge_accum(acc, __int_as_float(p3.y), ft, p3.x, lane);
    }
    for (; j < e; j++) {
        int2 p = ep[j];
        edge_accum(acc, __int_as_float(p.y), ft, p.x, lane);
    }
    return acc;
}

__device__ __forceinline__ void store_aggh(__half* __restrict__ dst, int warp,
                                           int lane, float4 a)
{
    __half2 h0 = __floats2half2_rn(a.x, a.y);
    __half2 h1 = __floats2half2_rn(a.z, a.w);
    uint2 u; u.x = *(unsigned*)&h0; u.y = *(unsigned*)&h1;
    ((uint2*)(dst + (size_t)warp * 128))[lane] = u;
}

// ---- K5a: gather rel0+rel1 + attention -> aggh[0] (standalone) ----
__global__ void __launch_bounds__(256) gather_attn_k(
    const int2* __restrict__ epack, const int* __restrict__ basebase,
    const __half* __restrict__ fth, const __half* __restrict__ xh,
    const float* __restrict__ uv, __half* __restrict__ aggh)
{
    int warp = (blockIdx.x * blockDim.x + threadIdx.x) >> 5;
    int lane = threadIdx.x & 31;
    if (warp >= NROW) return;

    float4 b = gather_row(epack, basebase, warp, fth, lane);
    float4 c = gather_row(epack + EDG, basebase + (NROW + 1), warp,
                          fth + (size_t)NROW * 128, lane);

    float4 u4 = ((const float4*)uv)[lane];
    const __half2* xrow = (const __half2*)(xh + (size_t)warp * 256);
    float4 w0 = ((const float4*)(uv + 256))[lane * 2];
    float4 w1 = ((const float4*)(uv + 256))[lane * 2 + 1];
    float2 q0 = __half22float2(xrow[lane * 4 + 0]);
    float2 q1 = __half22float2(xrow[lane * 4 + 1]);
    float2 q2 = __half22float2(xrow[lane * 4 + 2]);
    float2 q3 = __half22float2(xrow[lane * 4 + 3]);

    float db = b.x * u4.x + b.y * u4.y + b.z * u4.z + b.w * u4.w;
    float dc = c.x * u4.x + c.y * u4.y + c.z * u4.z + c.w * u4.w;
    float ds = q0.x * w0.x + q0.y * w0.y + q1.x * w0.z + q1.y * w0.w
             + q2.x * w1.x + q2.y * w1.y + q3.x * w1.z + q3.y * w1.w;

    #pragma unroll
    for (int o = 16; o; o >>= 1) {
        db += __shfl_xor_sync(0xffffffffu, db, o);
        dc += __shfl_xor_sync(0xffffffffu, dc, o);
        ds += __shfl_xor_sync(0xffffffffu, ds, o);
    }

    float eb = db + ds;
    float ec = dc + ds;
    eb = (eb > 0.f) ? eb : expm1f(eb);
    ec = (ec > 0.f) ? ec : expm1f(ec);
    float m  = fmaxf(eb, ec);
    float wb = expf(eb - m);
    float wc = expf(ec - m);
    float ab = wb / (wb + wc);
    float ac = 1.f - ab;

    float4 o4;
    o4.x = ab * b.x + ac * c.x;
    o4.y = ab * b.y + ac * c.y;
    o4.z = ab * b.z + ac * c.z;
    o4.w = ab * b.w + ac * c.w;
    store_aggh(aggh, warp, lane, o4);
}

// ---- K5b: gemm_out(y=0) || gather rel2,3 -> aggh[1],aggh[2] ----
__global__ void __launch_bounds__(256, 2) gemmy0_gather23(
    const __half* __restrict__ aggh, const __half* __restrict__ xh,
    const __half* __restrict__ Wcomb,
    const float* __restrict__ ba, const float* __restrict__ bb,
    const float* __restrict__ bc, float* __restrict__ outbase,
    const int2* __restrict__ epack, const int* __restrict__ basebase,
    const __half* __restrict__ fth, __half* __restrict__ aggh_w)
{
    int bid = blockIdx.x;
    if (bid < GB) {
        gemm_out_body(0, bid, aggh, xh, Wcomb, ba, bb, bc, outbase);
        return;
    }
    bid -= GB;
    int rel = 2 + bid / GWB;
    int warp = (bid % GWB) * 8 + (threadIdx.x >> 5);
    int lane = threadIdx.x & 31;
    if (warp >= NROW) return;
    float4 a = gather_row(epack + (size_t)rel * EDG,
                          basebase + rel * (NROW + 1),
                          warp, fth + (size_t)rel * NROW * 128, lane);
    store_aggh(aggh_w + (size_t)(rel - 1) * NROW * 128, warp, lane, a);
}

// ---- K6: gemm_out(y=1,2) ----
__global__ void __launch_bounds__(256, 2) gemmy12(
    const __half* __restrict__ aggh, const __half* __restrict__ xh,
    const __half* __restrict__ Wcomb,
    const float* __restrict__ ba, const float* __restrict__ bb,
    const float* __restrict__ bc, float* __restrict__ outbase)
{
    int y = 1 + blockIdx.x / GB;
    int bx = blockIdx.x % GB;
    gemm_out_body(y, bx, aggh, xh, Wcomb, ba, bb, bc, outbase);
}

// ================= launcher ===============================================
extern "C" void kernel_launch(void* const* d_in, const int* in_sizes, int n_in,
                              void* d_out, int out_size)
{
    const float* x_a       = (const float*)d_in[0];
    const float* x_b       = (const float*)d_in[1];
    const float* x_c       = (const float*)d_in[2];
    const int*   row_ab    = (const int*)d_in[3];
    const int*   col_ab    = (const int*)d_in[4];
    const float* val_ab    = (const float*)d_in[5];
    const int*   row_ac    = (const int*)d_in[6];
    const int*   col_ac    = (const int*)d_in[7];
    const float* val_ac    = (const float*)d_in[8];
    const int*   row_ba    = (const int*)d_in[9];
    const int*   col_ba    = (const int*)d_in[10];
    const float* val_ba    = (const float*)d_in[11];
    const int*   row_ca    = (const int*)d_in[12];
    const int*   col_ca    = (const int*)d_in[13];
    const float* val_ca    = (const float*)d_in[14];
    const float* w_self_a  = (const float*)d_in[15];
    const float* w_self_b  = (const float*)d_in[16];
    const float* w_self_c  = (const float*)d_in[17];
    const float* W_ab      = (const float*)d_in[18];
    const float* W_ac      = (const float*)d_in[19];
    const float* W_ba      = (const float*)d_in[20];
    const float* W_ca      = (const float*)d_in[21];
    const float* bias_a    = (const float*)d_in[22];
    const float* bias_b    = (const float*)d_in[23];
    const float* bias_c    = (const float*)d_in[24];
    const float* w_cat_a   = (const float*)d_in[25];
    const float* w_cat_b   = (const float*)d_in[26];
    const float* w_cat_c   = (const float*)d_in[27];
    const float* w_query_a = (const float*)d_in[28];
    const float* w_keys_a  = (const float*)d_in[29];
    const float* w_att_a   = (const float*)d_in[30];

    float* scratch = nullptr;
    cudaGetSymbolAddress((void**)&scratch, g_scratch);

    __half*   aggh    = (__half*)(scratch + OFF_AGGH);
    __half*   fth     = (__half*)(scratch + OFF_FTH);
    __half*   xh      = (__half*)(scratch + OFF_XH);
    __half*   Wh      = (__half*)(scratch + OFF_WH);
    __half*   Wcomb   = (__half*)(scratch + OFF_WCOMB);
    float*    uv      = scratch + OFF_UV;
    int*      deg     = (int*)(scratch + OFF_DEG);
    int*      base    = (int*)(scratch + OFF_BASE);
    int*      cur     = (int*)(scratch + OFF_CUR);
    int2*     epack   = (int2*)(scratch + OFF_EPACK);

    float* out = (float*)d_out;

    const int PREPB = CONVB + WHB + WC1B + FOLDB + UVB + ZEROB;

    // K1: prep (conversions, weight folds, uv/wv, zero deg)
    mega_prep<<<PREPB, 256>>>(x_a, x_b, x_c, (uint2*)xh,
                              W_ab, W_ac, W_ba, W_ca, Wh,
                              w_cat_a, w_cat_b, w_cat_c,
                              w_self_a, w_self_b, w_self_c, Wcomb,
                              w_query_a, w_keys_a, w_att_a, uv, deg);

    // K2: 4 projection GEMMs (fp16) + degree histogram
    mega_proj_hist<<<GEMMB + HISTB, 256>>>(xh, Wh, fth,
                                           row_ab, row_ac, row_ba, row_ca, deg);

    // K3: exclusive scan per relation
    exscan4<<<4, 1024>>>(deg, base, cur);

    // K4: scatter all 4 relations (2 edges/thread)
    scatter4<<<dim3(SCB, 4), 256>>>(row_ab, col_ab, val_ab,
                                    row_ac, col_ac, val_ac,
                                    row_ba, col_ba, val_ba,
                                    row_ca, col_ca, val_ca,
                                    cur, epack);

    // K5a: gather rel0+1 + attention -> aggh[0]
    gather_attn_k<<<GWB, 256>>>(epack, base, fth, xh, uv, aggh);

    // K5b: gemm_out(type a)  ||  gather rel2,3 -> aggh[1],aggh[2]
    gemmy0_gather23<<<GB + 2 * GWB, 256>>>(
        aggh, xh, Wcomb, bias_a, bias_b, bias_c, out,
        epack, base, fth, aggh);

    // K6: gemm_out(types b,c)
    gemmy12<<<2 * GB, 256>>>(aggh, xh, Wcomb, bias_a, bias_b, bias_c, out);
}

// round 13
// speedup vs baseline: 1.0829x; 1.0829x over previous
#include <cuda_runtime.h>
#include <cuda_fp16.h>
#include <cstdint>
#include <cstddef>

// ---------------- problem constants ----------------
#define NA 50000
#define NROW 50000
#define EDG 800000
#define EHALF (EDG / 2)
#define SZ (50000 * 128)        // floats per [N,128] fp32-equivalent slot
#define SZH (50000 * 128)       // halves per [N,128] fp16 buffer
#define XQ4 3200000             // float4 count per x array (50000*256/4)

#define GB 391                  // gemm blocks per matrix (128-row tiles)
#define GWB 6250                // gather blocks per relation (8 rows/block)
#define SCB 1563                // scatter blocks per relation (2 edges/thread)

// scratch layout (float units):
#define OFF_AGGH   0ull                           // 3 x [N,128] fp16 (1.5 slots)
#define OFF_FTH    (2ull * SZ)                    // 4 x [N,128] fp16 (2 slots)
#define OFF_XH     (4ull * SZ)                    // 3 x [N,256] fp16 (3 slots)
#define W_OFF      (7ull * SZ)
#define OFF_WH     (W_OFF)                        // 4*256*128 halves = 65536 floats
#define OFF_WCOMB  (OFF_WH + 65536)               // 3*384*128 halves = 73728 floats
#define OFF_UV     (OFF_WCOMB + 73728)            // 512 floats
#define OFF_DEG    (OFF_UV   + 512)
#define OFF_BASE   (OFF_DEG  + 4*50000)
#define OFF_CUR    (OFF_BASE + 4*50004)
#define OFF_EPACK  (((OFF_CUR + 4*50000) + 3) & ~3ull)   // 16B-aligned
#define OFF_NBH    (OFF_EPACK + 4ull*EDG*2)       // 2 x [N,128] fp16 (1 slot)
#define SCRATCH_TOTAL (OFF_NBH + 1ull * SZ)

__device__ __align__(256) float g_scratch[SCRATCH_TOTAL];

// ---------------- helpers ----------------
__device__ __forceinline__ void ldsm4(unsigned &r0, unsigned &r1, unsigned &r2,
                                      unsigned &r3, unsigned addr) {
    asm volatile("ldmatrix.sync.aligned.m8n8.x4.shared.b16 {%0,%1,%2,%3}, [%4];"
                 : "=r"(r0), "=r"(r1), "=r"(r2), "=r"(r3) : "r"(addr));
}

__device__ __forceinline__ void ldsm4t(unsigned &r0, unsigned &r1, unsigned &r2,
                                       unsigned &r3, unsigned addr) {
    asm volatile("ldmatrix.sync.aligned.m8n8.x4.trans.shared.b16 {%0,%1,%2,%3}, [%4];"
                 : "=r"(r0), "=r"(r1), "=r"(r2), "=r"(r3) : "r"(addr));
}

__device__ __forceinline__ void mma_f16(float c[4], const unsigned a[4],
                                        unsigned b0, unsigned b1) {
    asm volatile(
        "mma.sync.aligned.m16n8k16.row.col.f32.f16.f16.f32 "
        "{%0,%1,%2,%3}, {%4,%5,%6,%7}, {%8,%9}, {%0,%1,%2,%3};"
        : "+f"(c[0]), "+f"(c[1]), "+f"(c[2]), "+f"(c[3])
        : "r"(a[0]), "r"(a[1]), "r"(a[2]), "r"(a[3]), "r"(b0), "r"(b1));
}

__device__ __forceinline__ void cpasync16(void* sdst, const void* gsrc, int nbytes) {
    unsigned s = (unsigned)__cvta_generic_to_shared(sdst);
    asm volatile("cp.async.cg.shared.global [%0], [%1], 16, %2;\n"
                 :: "r"(s), "l"(gsrc), "r"(nbytes));
}

// ================= fp16 GEMM body (K-tiles of 32) =========================
template<int NKT, bool HOUT, bool SPLIT>
__device__ __forceinline__ void gemm_f16_body(
    const __half* __restrict__ A0, int lda0,
    const __half* __restrict__ A1, int lda1,
    const __half* __restrict__ B,                     // [K][128] row-major
    const float* __restrict__ bias,
    __half* __restrict__ Yh, float* __restrict__ Yf, int bx)
{
    __shared__ __half As[2][128][40];    // 32 k + 8 pad
    __shared__ __half Bs[2][32][136];    // [k][n], 128 n + 8 pad

    const int tid  = threadIdx.x;
    const int lane = tid & 31;
    const int w    = tid >> 5;
    const int bm   = bx * 128;

    const int wm = (w >> 2) * 64;
    const int wn = (w & 3) * 32;

    float acc[4][4][4];
    #pragma unroll
    for (int i = 0; i < 4; i++)
        #pragma unroll
        for (int j = 0; j < 4; j++)
            #pragma unroll
            for (int c = 0; c < 4; c++) acc[i][j][c] = 0.f;

    auto stage = [&](int buf, int k0) {
        const __half* asrc; int ld, col;
        if (SPLIT && k0 >= 128) { asrc = A1; ld = lda1; col = k0 - 128; }
        else                    { asrc = A0; ld = lda0; col = k0; }
        #pragma unroll
        for (int i = 0; i < 2; i++) {
            int slot = tid + i * 256;
            int r = slot >> 2, c = (slot & 3) * 8;
            int grow = bm + r;
            const __half* src = asrc + (size_t)(grow < NA ? grow : 0) * ld + col + c;
            cpasync16(&As[buf][r][c], src, grow < NA ? 16 : 0);
        }
        #pragma unroll
        for (int i = 0; i < 2; i++) {
            int slot = tid + i * 256;
            int r = slot >> 4, c = (slot & 15) * 8;
            cpasync16(&Bs[buf][r][c], B + (size_t)(k0 + r) * 128 + c, 16);
        }
        asm volatile("cp.async.commit_group;\n" ::);
    };

    stage(0, 0);

    for (int kt = 0; kt < NKT; kt++) {
        if (kt + 1 < NKT) {
            stage((kt + 1) & 1, (kt + 1) * 32);
            asm volatile("cp.async.wait_group 1;\n" ::);
        } else {
            asm volatile("cp.async.wait_group 0;\n" ::);
        }
        __syncthreads();

        const int buf = kt & 1;
        #pragma unroll
        for (int ks = 0; ks < 2; ks++) {
            const int k16 = ks * 16;
            unsigned a[4][4], b0[4], b1[4];
            #pragma unroll
            for (int mt = 0; mt < 4; mt++) {
                unsigned addr = (unsigned)__cvta_generic_to_shared(
                    &As[buf][wm + mt * 16 + (lane & 15)][k16 + (lane >> 4) * 8]);
                ldsm4(a[mt][0], a[mt][1], a[mt][2], a[mt][3], addr);
            }
            #pragma unroll
            for (int np = 0; np < 2; np++) {
                unsigned addr = (unsigned)__cvta_generic_to_shared(
                    &Bs[buf][k16 + (lane & 15)][wn + np * 16 + (lane >> 4) * 8]);
                ldsm4t(b0[np * 2], b1[np * 2], b0[np * 2 + 1], b1[np * 2 + 1], addr);
            }
            #pragma unroll
            for (int mt = 0; mt < 4; mt++)
                #pragma unroll
                for (int nt = 0; nt < 4; nt++)
                    mma_f16(acc[mt][nt], a[mt], b0[nt], b1[nt]);
        }
        __syncthreads();
    }

    const int g = lane >> 2, tg = lane & 3;
    #pragma unroll
    for (int nt = 0; nt < 4; nt++) {
        int cc = wn + nt * 8 + tg * 2;
        float bx0 = HOUT ? 0.f : bias[cc];
        float bx1 = HOUT ? 0.f : bias[cc + 1];
        #pragma unroll
        for (int mt = 0; mt < 4; mt++) {
            int r = bm + wm + mt * 16 + g;
            if (r < NA) {
                if (HOUT)
                    *(__half2*)(Yh + (size_t)r * 128 + cc) =
                        __floats2half2_rn(acc[mt][nt][0], acc[mt][nt][1]);
                else
                    *(float2*)(Yf + (size_t)r * 128 + cc) =
                        make_float2(acc[mt][nt][0] + bx0, acc[mt][nt][1] + bx1);
            }
            if (r + 8 < NA) {
                if (HOUT)
                    *(__half2*)(Yh + (size_t)(r + 8) * 128 + cc) =
                        __floats2half2_rn(acc[mt][nt][2], acc[mt][nt][3]);
                else
                    *(float2*)(Yf + (size_t)(r + 8) * 128 + cc) =
                        make_float2(acc[mt][nt][2] + bx0, acc[mt][nt][3] + bx1);
            }
        }
    }
}

// ---- proj GEMMs (4) + degree hist in one grid (verbatim R8) ----
#define GEMMB 1564   // 391*4
#define HISTB 512
__global__ void __launch_bounds__(256, 2) mega_proj_hist(
    const __half* __restrict__ xh, const __half* __restrict__ Wh,
    __half* __restrict__ fth,
    const int* __restrict__ r0, const int* __restrict__ r1,
    const int* __restrict__ r2, const int* __restrict__ r3,
    int* __restrict__ deg)
{
    int bid = blockIdx.x;
    if (bid < GEMMB) {
        int y = bid / 391;
        int bx = bid - y * 391;
        const __half* A = (y == 0) ? xh + 1ull * NROW * 256
                        : (y == 1) ? xh + 2ull * NROW * 256
                                   : xh;
        gemm_f16_body<8, true, false>(A, 256, nullptr, 0,
                                      Wh + (size_t)y * 256 * 128, nullptr,
                                      fth + (size_t)y * NROW * 128, nullptr, bx);
    } else {
        int hb = bid - GEMMB;
        for (int i = hb * 256 + threadIdx.x; i < 4 * EDG; i += HISTB * 256) {
            int rel = i / EDG;
            int e   = i - rel * EDG;
            const int* row = (rel == 0) ? r0 : (rel == 1) ? r1 : (rel == 2) ? r2 : r3;
            atomicAdd(&deg[rel * NROW + row[e]], 1);
        }
    }
}

// ---- output GEMM body (selects per-type pointers) ----
__device__ __forceinline__ void gemm_out_body(
    int y, int bx,
    const __half* __restrict__ aggh, const __half* __restrict__ xh,
    const __half* __restrict__ Wcomb,
    const float* __restrict__ ba, const float* __restrict__ bb,
    const float* __restrict__ bc, float* __restrict__ outbase)
{
    const float* bias = (y == 0) ? ba : (y == 1) ? bb : bc;
    gemm_f16_body<12, false, true>(
        aggh + (size_t)y * NROW * 128, 128,
        xh   + (size_t)y * NROW * 256, 256,
        Wcomb + (size_t)y * 384 * 128,
        bias, nullptr, outbase + (size_t)y * NROW * 128, bx);
}

// ================= mega prep kernel (verbatim R8) =========================
#define CONVB 2048
#define WHB   512
#define WC1B  192
#define FOLDB 384
#define UVB   1
#define ZEROB 782
__global__ void mega_prep(
    const float* __restrict__ xa, const float* __restrict__ xb,
    const float* __restrict__ xc, uint2* __restrict__ xh_u2,
    const float* __restrict__ Wab, const float* __restrict__ Wac,
    const float* __restrict__ Wba, const float* __restrict__ Wca,
    __half* __restrict__ Wh,
    const float* __restrict__ wca_, const float* __restrict__ wcb_,
    const float* __restrict__ wcc_,
    const float* __restrict__ wsa, const float* __restrict__ wsb,
    const float* __restrict__ wsc, __half* __restrict__ Wcomb,
    const float* __restrict__ wq, const float* __restrict__ wk,
    const float* __restrict__ watt, float* __restrict__ uv,
    int* __restrict__ deg)
{
    int bid = blockIdx.x;
    int tid = threadIdx.x;

    if (bid < CONVB) {
        for (int i = bid * 256 + tid; i < 3 * XQ4; i += CONVB * 256) {
            int arr = i / XQ4;
            int off = i - arr * XQ4;
            const float* src = (arr == 0) ? xa : (arr == 1) ? xb : xc;
            float4 v = ((const float4*)src)[off];
            __half2 h0 = __floats2half2_rn(v.x, v.y);
            __half2 h1 = __floats2half2_rn(v.z, v.w);
            uint2 u;
            u.x = *(unsigned*)&h0;
            u.y = *(unsigned*)&h1;
            xh_u2[(size_t)arr * XQ4 + off] = u;
        }
        return;
    }
    bid -= CONVB;
    if (bid < WHB) {
        int rel = bid >> 7, blk = bid & 127;
        const float* W = (rel == 0) ? Wab : (rel == 1) ? Wac : (rel == 2) ? Wba : Wca;
        int idx = blk * 256 + tid;
        Wh[(size_t)rel * 32768 + idx] = __float2half(W[idx]);
        return;
    }
    bid -= WHB;
    if (bid < WC1B) {
        int m = bid / 64, blk = bid - m * 64;
        const float* wc = (m == 0) ? wca_ : (m == 1) ? wcb_ : wcc_;
        int idx = blk * 256 + tid;   // 0..16383
        Wcomb[(size_t)m * 49152 + idx] = __float2half(wc[idx]);
        return;
    }
    bid -= WC1B;
    if (bid < FOLDB) {
        int m = bid >> 7, blk = bid & 127;
        const float* ws = (m == 0) ? wsa : (m == 1) ? wsb : wsc;
        const float* wc = ((m == 0) ? wca_ : (m == 1) ? wcb_ : wcc_) + 128 * 128;
        int idx = blk * 256 + tid;   // 0..32767
        int k = idx >> 7, n = idx & 127;
        float s = 0.f;
        #pragma unroll 8
        for (int j = 0; j < 128; j++) s += ws[k * 128 + j] * wc[j * 128 + n];
        Wcomb[(size_t)m * 49152 + (128 + k) * 128 + n] = __float2half(s);
        return;
    }
    bid -= FOLDB;
    if (bid < UVB) {
        if (tid < 128) {
            float s = 0.f;
            #pragma unroll
            for (int j = 0; j < 64; j++) s += wk[tid * 64 + j] * watt[j];
            uv[tid] = s;
        } else {
            int i = tid - 128;
            float s = 0.f;
            #pragma unroll
            for (int j = 0; j < 64; j++) s += wq[i * 64 + j] * watt[64 + j];
            uv[128 + i] = s;
        }
        __syncthreads();
        {
            const float* v = uv + 128;
            float s = 0.f;
            #pragma unroll 8
            for (int j = 0; j < 128; j++) s += wsa[tid * 128 + j] * v[j];
            uv[256 + tid] = s;
        }
        return;
    }
    bid -= UVB;
    {
        int i = bid * 256 + tid;
        if (i < 4 * NROW) deg[i] = 0;
    }
}

// ================= CSR: scan + scatter (verbatim R8) ======================
__global__ void __launch_bounds__(1024) exscan4(const int* __restrict__ degbase,
                                                int* __restrict__ basebase,
                                                int* __restrict__ curbase)
{
    const int* deg = degbase + blockIdx.x * NROW;
    int* base = basebase + blockIdx.x * (NROW + 1);
    int* cur  = curbase  + blockIdx.x * NROW;

    __shared__ int wsum[32];
    __shared__ int carry;
    int tid = threadIdx.x, lane = tid & 31, wid = tid >> 5;
    if (tid == 0) carry = 0;
    __syncthreads();

    for (int start = 0; start < NROW; start += 1024) {
        int i = start + tid;
        int v = (i < NROW) ? deg[i] : 0;
        int x = v;
        #pragma unroll
        for (int off = 1; off < 32; off <<= 1) {
            int t = __shfl_up_sync(0xffffffffu, x, off);
            if (lane >= off) x += t;
        }
        if (lane == 31) wsum[wid] = x;
        __syncthreads();
        if (wid == 0) {
            int s = wsum[lane];
            #pragma unroll
            for (int off = 1; off < 32; off <<= 1) {
                int t = __shfl_up_sync(0xffffffffu, s, off);
                if (lane >= off) s += t;
            }
            wsum[lane] = s;
        }
        __syncthreads();
        int incl = x + (wid ? wsum[wid - 1] : 0) + carry;
        if (i < NROW) { base[i] = incl - v; cur[i] = incl - v; }
        __syncthreads();
        if (tid == 0) carry += wsum[31];
        __syncthreads();
    }
    if (threadIdx.x == 0) base[NROW] = carry;
}

__global__ void scatter4(const int* __restrict__ r0, const int* __restrict__ c0, const float* __restrict__ v0,
                         const int* __restrict__ r1, const int* __restrict__ c1, const float* __restrict__ v1,
                         const int* __restrict__ r2, const int* __restrict__ c2, const float* __restrict__ v2,
                         const int* __restrict__ r3, const int* __restrict__ c3, const float* __restrict__ v3,
                         int* __restrict__ curbase, int2* __restrict__ epackbase)
{
    const int* row; const int* col; const float* val;
    switch (blockIdx.y) {
        case 0: row = r0; col = c0; val = v0; break;
        case 1: row = r1; col = c1; val = v1; break;
        case 2: row = r2; col = c2; val = v2; break;
        default: row = r3; col = c3; val = v3; break;
    }
    int* cur = curbase + blockIdx.y * NROW;
    int2* ep = epackbase + (size_t)blockIdx.y * EDG;
    int i = blockIdx.x * blockDim.x + threadIdx.x;
    if (i >= EHALF) return;
    int ra = row[i],         rb = row[i + EHALF];
    int ca = col[i],         cb = col[i + EHALF];
    float va = val[i],       vb = val[i + EHALF];
    int pa = atomicAdd(&cur[ra], 1);
    int pb = atomicAdd(&cur[rb], 1);
    ep[pa] = make_int2(ca, __float_as_int(va));
    ep[pb] = make_int2(cb, __float_as_int(vb));
}

// ================= gather primitives (verbatim R8) ========================
__device__ __forceinline__ void edge_accum(float4& acc, float v,
                                           const __half* __restrict__ ft,
                                           int c, int lane)
{
    uint2 u = ((const uint2*)(ft + (size_t)c * 128))[lane];
    float2 l0 = __half22float2(*(__half2*)&u.x);
    float2 l1 = __half22float2(*(__half2*)&u.y);
    acc.x += v * l0.x; acc.y += v * l0.y;
    acc.z += v * l1.x; acc.w += v * l1.y;
}

__device__ __forceinline__ float4 gather_row(
    const int2* __restrict__ ep, const int* __restrict__ base,
    int r, const __half* __restrict__ ft, int lane)
{
    int s = base[r], e = base[r + 1];
    float4 acc = make_float4(0.f, 0.f, 0.f, 0.f);
    int j = s;
    for (; j + 3 < e; j += 4) {
        int2 p0 = ep[j],     p1 = ep[j + 1];
        int2 p2 = ep[j + 2], p3 = ep[j + 3];
        edge_accum(acc, __int_as_float(p0.y), ft, p0.x, lane);
        edge_accum(acc, __int_as_float(p1.y), ft, p1.x, lane);
        edge_accum(acc, __int_as_float(p2.y), ft, p2.x, lane);
        edge_accum(acc, __int_as_float(p3.y), ft, p3.x, lane);
    }
    for (; j < e; j++) {
        int2 p = ep[j];
        edge_accum(acc, __int_as_float(p.y), ft, p.x, lane);
    }
    return acc;
}

__device__ __forceinline__ void store_h128(__half* __restrict__ dst, int warp,
                                           int lane, float4 a)
{
    __half2 h0 = __floats2half2_rn(a.x, a.y);
    __half2 h1 = __floats2half2_rn(a.z, a.w);
    uint2 u; u.x = *(unsigned*)&h0; u.y = *(unsigned*)&h1;
    ((uint2*)(dst + (size_t)warp * 128))[lane] = u;
}

// ---- K5: balanced gather — one relation per block-slice ----
// rel0 -> nbh[0], rel1 -> nbh[1], rel2 -> aggh[1], rel3 -> aggh[2]
__global__ void __launch_bounds__(256) gather4_bal(
    const int2* __restrict__ epack, const int* __restrict__ basebase,
    const __half* __restrict__ fth, __half* __restrict__ nbh,
    __half* __restrict__ aggh)
{
    int bid = blockIdx.x;
    int rel = bid / GWB;
    int warp = (bid - rel * GWB) * 8 + (threadIdx.x >> 5);
    int lane = threadIdx.x & 31;
    if (warp >= NROW) return;

    float4 a = gather_row(epack + (size_t)rel * EDG,
                          basebase + rel * (NROW + 1),
                          warp, fth + (size_t)rel * SZH, lane);
    __half* dst = (rel == 0) ? nbh
                : (rel == 1) ? nbh + (size_t)SZH
                : (rel == 2) ? aggh + (size_t)SZH
                             : aggh + 2ull * SZH;
    store_h128(dst, warp, lane, a);
}

// ---- K6: attention (reads nbh) -> aggh[0]  ||  gemm_out(y=1,2) ----
__global__ void __launch_bounds__(256, 2) attn_gemmy12(
    const __half* __restrict__ nbh, const __half* __restrict__ xh,
    const float* __restrict__ uv, __half* __restrict__ aggh,
    const __half* __restrict__ Wcomb,
    const float* __restrict__ ba, const float* __restrict__ bb,
    const float* __restrict__ bc, float* __restrict__ outbase)
{
    int bid = blockIdx.x;
    if (bid >= GWB) {
        bid -= GWB;
        int y = 1 + bid / GB;
        gemm_out_body(y, bid % GB, aggh, xh, Wcomb, ba, bb, bc, outbase);
        return;
    }
    int warp = bid * 8 + (threadIdx.x >> 5);
    int lane = threadIdx.x & 31;
    if (warp >= NROW) return;

    // load gathered neighbor rows (fp16)
    uint2 ub = ((const uint2*)(nbh + (size_t)warp * 128))[lane];
    uint2 uc = ((const uint2*)(nbh + (size_t)SZH + (size_t)warp * 128))[lane];
    float2 b0 = __half22float2(*(__half2*)&ub.x);
    float2 b1 = __half22float2(*(__half2*)&ub.y);
    float2 c0 = __half22float2(*(__half2*)&uc.x);
    float2 c1 = __half22float2(*(__half2*)&uc.y);
    float4 b = make_float4(b0.x, b0.y, b1.x, b1.y);
    float4 c = make_float4(c0.x, c0.y, c1.x, c1.y);

    float4 u4 = ((const float4*)uv)[lane];
    const __half2* xrow = (const __half2*)(xh + (size_t)warp * 256);
    float4 w0 = ((const float4*)(uv + 256))[lane * 2];
    float4 w1 = ((const float4*)(uv + 256))[lane * 2 + 1];
    float2 q0 = __half22float2(xrow[lane * 4 + 0]);
    float2 q1 = __half22float2(xrow[lane * 4 + 1]);
    float2 q2 = __half22float2(xrow[lane * 4 + 2]);
    float2 q3 = __half22float2(xrow[lane * 4 + 3]);

    float db = b.x * u4.x + b.y * u4.y + b.z * u4.z + b.w * u4.w;
    float dc = c.x * u4.x + c.y * u4.y + c.z * u4.z + c.w * u4.w;
    float ds = q0.x * w0.x + q0.y * w0.y + q1.x * w0.z + q1.y * w0.w
             + q2.x * w1.x + q2.y * w1.y + q3.x * w1.z + q3.y * w1.w;

    #pragma unroll
    for (int o = 16; o; o >>= 1) {
        db += __shfl_xor_sync(0xffffffffu, db, o);
        dc += __shfl_xor_sync(0xffffffffu, dc, o);
        ds += __shfl_xor_sync(0xffffffffu, ds, o);
    }

    float eb = db + ds;
    float ec = dc + ds;
    eb = (eb > 0.f) ? eb : expm1f(eb);
    ec = (ec > 0.f) ? ec : expm1f(ec);
    float m  = fmaxf(eb, ec);
    float wb = expf(eb - m);
    float wc = expf(ec - m);
    float ab = wb / (wb + wc);
    float ac = 1.f - ab;

    float4 o4;
    o4.x = ab * b.x + ac * c.x;
    o4.y = ab * b.y + ac * c.y;
    o4.z = ab * b.z + ac * c.z;
    o4.w = ab * b.w + ac * c.w;
    store_h128(aggh, warp, lane, o4);
}

// ---- K7: gemm_out(y=0) ----
__global__ void __launch_bounds__(256, 2) gemmy0(
    const __half* __restrict__ aggh, const __half* __restrict__ xh,
    const __half* __restrict__ Wcomb,
    const float* __restrict__ ba, const float* __restrict__ bb,
    const float* __restrict__ bc, float* __restrict__ outbase)
{
    gemm_out_body(0, blockIdx.x, aggh, xh, Wcomb, ba, bb, bc, outbase);
}

// ================= launcher ===============================================
extern "C" void kernel_launch(void* const* d_in, const int* in_sizes, int n_in,
                              void* d_out, int out_size)
{
    const float* x_a       = (const float*)d_in[0];
    const float* x_b       = (const float*)d_in[1];
    const float* x_c       = (const float*)d_in[2];
    const int*   row_ab    = (const int*)d_in[3];
    const int*   col_ab    = (const int*)d_in[4];
    const float* val_ab    = (const float*)d_in[5];
    const int*   row_ac    = (const int*)d_in[6];
    const int*   col_ac    = (const int*)d_in[7];
    const float* val_ac    = (const float*)d_in[8];
    const int*   row_ba    = (const int*)d_in[9];
    const int*   col_ba    = (const int*)d_in[10];
    const float* val_ba    = (const float*)d_in[11];
    const int*   row_ca    = (const int*)d_in[12];
    const int*   col_ca    = (const int*)d_in[13];
    const float* val_ca    = (const float*)d_in[14];
    const float* w_self_a  = (const float*)d_in[15];
    const float* w_self_b  = (const float*)d_in[16];
    const float* w_self_c  = (const float*)d_in[17];
    const float* W_ab      = (const float*)d_in[18];
    const float* W_ac      = (const float*)d_in[19];
    const float* W_ba      = (const float*)d_in[20];
    const float* W_ca      = (const float*)d_in[21];
    const float* bias_a    = (const float*)d_in[22];
    const float* bias_b    = (const float*)d_in[23];
    const float* bias_c    = (const float*)d_in[24];
    const float* w_cat_a   = (const float*)d_in[25];
    const float* w_cat_b   = (const float*)d_in[26];
    const float* w_cat_c   = (const float*)d_in[27];
    const float* w_query_a = (const float*)d_in[28];
    const float* w_keys_a  = (const float*)d_in[29];
    const float* w_att_a   = (const float*)d_in[30];

    float* scratch = nullptr;
    cudaGetSymbolAddress((void**)&scratch, g_scratch);

    __half*   aggh    = (__half*)(scratch + OFF_AGGH);
    __half*   fth     = (__half*)(scratch + OFF_FTH);
    __half*   xh      = (__half*)(scratch + OFF_XH);
    __half*   Wh      = (__half*)(scratch + OFF_WH);
    __half*   Wcomb   = (__half*)(scratch + OFF_WCOMB);
    float*    uv      = scratch + OFF_UV;
    int*      deg     = (int*)(scratch + OFF_DEG);
    int*      base    = (int*)(scratch + OFF_BASE);
    int*      cur     = (int*)(scratch + OFF_CUR);
    int2*     epack   = (int2*)(scratch + OFF_EPACK);
    __half*   nbh     = (__half*)(scratch + OFF_NBH);

    float* out = (float*)d_out;

    const int PREPB = CONVB + WHB + WC1B + FOLDB + UVB + ZEROB;

    // K1: prep (conversions, weight folds, uv/wv, zero deg)
    mega_prep<<<PREPB, 256>>>(x_a, x_b, x_c, (uint2*)xh,
                              W_ab, W_ac, W_ba, W_ca, Wh,
                              w_cat_a, w_cat_b, w_cat_c,
                              w_self_a, w_self_b, w_self_c, Wcomb,
                              w_query_a, w_keys_a, w_att_a, uv, deg);

    // K2: 4 projection GEMMs (fp16) + degree histogram
    mega_proj_hist<<<GEMMB + HISTB, 256>>>(xh, Wh, fth,
                                           row_ab, row_ac, row_ba, row_ca, deg);

    // K3: exclusive scan per relation
    exscan4<<<4, 1024>>>(deg, base, cur);

    // K4: scatter all 4 relations (2 edges/thread)
    scatter4<<<dim3(SCB, 4), 256>>>(row_ab, col_ab, val_ab,
                                    row_ac, col_ac, val_ac,
                                    row_ba, col_ba, val_ba,
                                    row_ca, col_ca, val_ca,
                                    cur, epack);

    // K5: balanced gather — one relation per block-slice
    gather4_bal<<<4 * GWB, 256>>>(epack, base, fth, nbh, aggh);

    // K6: attention -> aggh[0]  ||  gemm_out(y=1,2)
    attn_gemmy12<<<GWB + 2 * GB, 256>>>(nbh, xh, uv, aggh, Wcomb,
                                        bias_a, bias_b, bias_c, out);

    // K7: gemm_out(y=0)
    gemmy0<<<GB, 256>>>(aggh, xh, Wcomb, bias_a, bias_b, bias_c, out);
}

// round 16
// speedup vs baseline: 1.2015x; 1.1095x over previous
#include <cuda_runtime.h>
#include <cuda_fp16.h>
#include <cstdint>
#include <cstddef>

// ---------------- problem constants ----------------
#define NA 50000
#define NROW 50000
#define EDG 800000
#define EHALF (EDG / 2)
#define SZ (50000 * 128)        // floats per [N,128] fp32-equivalent slot
#define XQ4 3200000             // float4 count per x array (50000*256/4)

#define GB 391                  // gemm blocks per matrix (128-row tiles)
#define GWB 6250                // gather blocks (8 rows/block)
#define SCB 1563                // scatter blocks per relation (2 edges/thread)

// scratch layout (float units):
#define OFF_AGGH   0ull                           // 3 x [N,128] fp16 (1.5 slots)
#define OFF_FTH    (2ull * SZ)                    // 4 x [N,128] fp16 (2 slots)
#define OFF_XH     (4ull * SZ)                    // 3 x [N,256] fp16 (3 slots)
#define W_OFF      (7ull * SZ)
#define OFF_WH     (W_OFF)                        // 4*256*128 halves = 65536 floats
#define OFF_WCOMB  (OFF_WH + 65536)               // 3*384*128 halves = 73728 floats
#define OFF_UV     (OFF_WCOMB + 73728)            // 512 floats
#define OFF_DEG    (OFF_UV   + 512)
#define OFF_BASE   (OFF_DEG  + 4*50000)
#define OFF_CUR    (OFF_BASE + 4*50004)
#define OFF_EPACK  (((OFF_CUR + 4*50000) + 3) & ~3ull)   // 16B-aligned
#define SCRATCH_TOTAL (OFF_EPACK + 4ull*EDG*2)

__device__ __align__(256) float g_scratch[SCRATCH_TOTAL];

// ---------------- helpers ----------------
__device__ __forceinline__ void ldsm4(unsigned &r0, unsigned &r1, unsigned &r2,
                                      unsigned &r3, unsigned addr) {
    asm volatile("ldmatrix.sync.aligned.m8n8.x4.shared.b16 {%0,%1,%2,%3}, [%4];"
                 : "=r"(r0), "=r"(r1), "=r"(r2), "=r"(r3) : "r"(addr));
}

__device__ __forceinline__ void ldsm4t(unsigned &r0, unsigned &r1, unsigned &r2,
                                       unsigned &r3, unsigned addr) {
    asm volatile("ldmatrix.sync.aligned.m8n8.x4.trans.shared.b16 {%0,%1,%2,%3}, [%4];"
                 : "=r"(r0), "=r"(r1), "=r"(r2), "=r"(r3) : "r"(addr));
}

__device__ __forceinline__ void mma_f16(float c[4], const unsigned a[4],
                                        unsigned b0, unsigned b1) {
    asm volatile(
        "mma.sync.aligned.m16n8k16.row.col.f32.f16.f16.f32 "
        "{%0,%1,%2,%3}, {%4,%5,%6,%7}, {%8,%9}, {%0,%1,%2,%3};"
        : "+f"(c[0]), "+f"(c[1]), "+f"(c[2]), "+f"(c[3])
        : "r"(a[0]), "r"(a[1]), "r"(a[2]), "r"(a[3]), "r"(b0), "r"(b1));
}

__device__ __forceinline__ void cpasync16(void* sdst, const void* gsrc, int nbytes) {
    unsigned s = (unsigned)__cvta_generic_to_shared(sdst);
    asm volatile("cp.async.cg.shared.global [%0], [%1], 16, %2;\n"
                 :: "r"(s), "l"(gsrc), "r"(nbytes));
}

// ================= fp16 GEMM body (K-tiles of 32) =========================
template<int NKT, bool HOUT, bool SPLIT>
__device__ __forceinline__ void gemm_f16_body(
    const __half* __restrict__ A0, int lda0,
    const __half* __restrict__ A1, int lda1,
    const __half* __restrict__ B,                     // [K][128] row-major
    const float* __restrict__ bias,
    __half* __restrict__ Yh, float* __restrict__ Yf, int bx)
{
    __shared__ __half As[2][128][40];    // 32 k + 8 pad
    __shared__ __half Bs[2][32][136];    // [k][n], 128 n + 8 pad

    const int tid  = threadIdx.x;
    const int lane = tid & 31;
    const int w    = tid >> 5;
    const int bm   = bx * 128;

    const int wm = (w >> 2) * 64;
    const int wn = (w & 3) * 32;

    float acc[4][4][4];
    #pragma unroll
    for (int i = 0; i < 4; i++)
        #pragma unroll
        for (int j = 0; j < 4; j++)
            #pragma unroll
            for (int c = 0; c < 4; c++) acc[i][j][c] = 0.f;

    auto stage = [&](int buf, int k0) {
        const __half* asrc; int ld, col;
        if (SPLIT && k0 >= 128) { asrc = A1; ld = lda1; col = k0 - 128; }
        else                    { asrc = A0; ld = lda0; col = k0; }
        #pragma unroll
        for (int i = 0; i < 2; i++) {
            int slot = tid + i * 256;
            int r = slot >> 2, c = (slot & 3) * 8;
            int grow = bm + r;
            const __half* src = asrc + (size_t)(grow < NA ? grow : 0) * ld + col + c;
            cpasync16(&As[buf][r][c], src, grow < NA ? 16 : 0);
        }
        #pragma unroll
        for (int i = 0; i < 2; i++) {
            int slot = tid + i * 256;
            int r = slot >> 4, c = (slot & 15) * 8;
            cpasync16(&Bs[buf][r][c], B + (size_t)(k0 + r) * 128 + c, 16);
        }
        asm volatile("cp.async.commit_group;\n" ::);
    };

    stage(0, 0);

    for (int kt = 0; kt < NKT; kt++) {
        if (kt + 1 < NKT) {
            stage((kt + 1) & 1, (kt + 1) * 32);
            asm volatile("cp.async.wait_group 1;\n" ::);
        } else {
            asm volatile("cp.async.wait_group 0;\n" ::);
        }
        __syncthreads();

        const int buf = kt & 1;
        #pragma unroll
        for (int ks = 0; ks < 2; ks++) {
            const int k16 = ks * 16;
            unsigned a[4][4], b0[4], b1[4];
            #pragma unroll
            for (int mt = 0; mt < 4; mt++) {
                unsigned addr = (unsigned)__cvta_generic_to_shared(
                    &As[buf][wm + mt * 16 + (lane & 15)][k16 + (lane >> 4) * 8]);
                ldsm4(a[mt][0], a[mt][1], a[mt][2], a[mt][3], addr);
            }
            #pragma unroll
            for (int np = 0; np < 2; np++) {
                unsigned addr = (unsigned)__cvta_generic_to_shared(
                    &Bs[buf][k16 + (lane & 15)][wn + np * 16 + (lane >> 4) * 8]);
                ldsm4t(b0[np * 2], b1[np * 2], b0[np * 2 + 1], b1[np * 2 + 1], addr);
            }
            #pragma unroll
            for (int mt = 0; mt < 4; mt++)
                #pragma unroll
                for (int nt = 0; nt < 4; nt++)
                    mma_f16(acc[mt][nt], a[mt], b0[nt], b1[nt]);
        }
        __syncthreads();
    }

    const int g = lane >> 2, tg = lane & 3;
    #pragma unroll
    for (int nt = 0; nt < 4; nt++) {
        int cc = wn + nt * 8 + tg * 2;
        float bx0 = HOUT ? 0.f : bias[cc];
        float bx1 = HOUT ? 0.f : bias[cc + 1];
        #pragma unroll
        for (int mt = 0; mt < 4; mt++) {
            int r = bm + wm + mt * 16 + g;
            if (r < NA) {
                if (HOUT)
                    *(__half2*)(Yh + (size_t)r * 128 + cc) =
                        __floats2half2_rn(acc[mt][nt][0], acc[mt][nt][1]);
                else
                    *(float2*)(Yf + (size_t)r * 128 + cc) =
                        make_float2(acc[mt][nt][0] + bx0, acc[mt][nt][1] + bx1);
            }
            if (r + 8 < NA) {
                if (HOUT)
                    *(__half2*)(Yh + (size_t)(r + 8) * 128 + cc) =
                        __floats2half2_rn(acc[mt][nt][2], acc[mt][nt][3]);
                else
                    *(float2*)(Yf + (size_t)(r + 8) * 128 + cc) =
                        make_float2(acc[mt][nt][2] + bx0, acc[mt][nt][3] + bx1);
            }
        }
    }
}

// ---- output GEMM body ----
__device__ __forceinline__ void gemm_out_body(
    int y, int bx,
    const __half* __restrict__ aggh, const __half* __restrict__ xh,
    const __half* __restrict__ Wcomb,
    const float* __restrict__ ba, const float* __restrict__ bb,
    const float* __restrict__ bc, float* __restrict__ outbase)
{
    const float* bias = (y == 0) ? ba : (y == 1) ? bb : bc;
    gemm_f16_body<12, false, true>(
        aggh + (size_t)y * NROW * 128, 128,
        xh   + (size_t)y * NROW * 256, 256,
        Wcomb + (size_t)y * 384 * 128,
        bias, nullptr, outbase + (size_t)y * NROW * 128, bx);
}

// ================= K1: mega prep (verbatim R8) ============================
#define CONVB 2048
#define WHB   512
#define WC1B  192
#define FOLDB 384
#define UVB   1
#define ZEROB 782
__global__ void mega_prep(
    const float* __restrict__ xa, const float* __restrict__ xb,
    const float* __restrict__ xc, uint2* __restrict__ xh_u2,
    const float* __restrict__ Wab, const float* __restrict__ Wac,
    const float* __restrict__ Wba, const float* __restrict__ Wca,
    __half* __restrict__ Wh,
    const float* __restrict__ wca_, const float* __restrict__ wcb_,
    const float* __restrict__ wcc_,
    const float* __restrict__ wsa, const float* __restrict__ wsb,
    const float* __restrict__ wsc, __half* __restrict__ Wcomb,
    const float* __restrict__ wq, const float* __restrict__ wk,
    const float* __restrict__ watt, float* __restrict__ uv,
    int* __restrict__ deg)
{
    int bid = blockIdx.x;
    int tid = threadIdx.x;

    if (bid < CONVB) {
        for (int i = bid * 256 + tid; i < 3 * XQ4; i += CONVB * 256) {
            int arr = i / XQ4;
            int off = i - arr * XQ4;
            const float* src = (arr == 0) ? xa : (arr == 1) ? xb : xc;
            float4 v = ((const float4*)src)[off];
            __half2 h0 = __floats2half2_rn(v.x, v.y);
            __half2 h1 = __floats2half2_rn(v.z, v.w);
            uint2 u;
            u.x = *(unsigned*)&h0;
            u.y = *(unsigned*)&h1;
            xh_u2[(size_t)arr * XQ4 + off] = u;
        }
        return;
    }
    bid -= CONVB;
    if (bid < WHB) {
        int rel = bid >> 7, blk = bid & 127;
        const float* W = (rel == 0) ? Wab : (rel == 1) ? Wac : (rel == 2) ? Wba : Wca;
        int idx = blk * 256 + tid;
        Wh[(size_t)rel * 32768 + idx] = __float2half(W[idx]);
        return;
    }
    bid -= WHB;
    if (bid < WC1B) {
        int m = bid / 64, blk = bid - m * 64;
        const float* wc = (m == 0) ? wca_ : (m == 1) ? wcb_ : wcc_;
        int idx = blk * 256 + tid;   // 0..16383
        Wcomb[(size_t)m * 49152 + idx] = __float2half(wc[idx]);
        return;
    }
    bid -= WC1B;
    if (bid < FOLDB) {
        int m = bid >> 7, blk = bid & 127;
        const float* ws = (m == 0) ? wsa : (m == 1) ? wsb : wsc;
        const float* wc = ((m == 0) ? wca_ : (m == 1) ? wcb_ : wcc_) + 128 * 128;
        int idx = blk * 256 + tid;   // 0..32767
        int k = idx >> 7, n = idx & 127;
        float s = 0.f;
        #pragma unroll 8
        for (int j = 0; j < 128; j++) s += ws[k * 128 + j] * wc[j * 128 + n];
        Wcomb[(size_t)m * 49152 + (128 + k) * 128 + n] = __float2half(s);
        return;
    }
    bid -= FOLDB;
    if (bid < UVB) {
        if (tid < 128) {
            float s = 0.f;
            #pragma unroll
            for (int j = 0; j < 64; j++) s += wk[tid * 64 + j] * watt[j];
            uv[tid] = s;
        } else {
            int i = tid - 128;
            float s = 0.f;
            #pragma unroll
            for (int j = 0; j < 64; j++) s += wq[i * 64 + j] * watt[64 + j];
            uv[128 + i] = s;
        }
        __syncthreads();
        {
            const float* v = uv + 128;
            float s = 0.f;
            #pragma unroll 8
            for (int j = 0; j < 128; j++) s += wsa[tid * 128 + j] * v[j];
            uv[256 + tid] = s;
        }
        return;
    }
    bid -= UVB;
    {
        int i = bid * 256 + tid;
        if (i < 4 * NROW) deg[i] = 0;
    }
}

// ================= K2: standalone degree histogram ========================
#define HISTB2 4096
__global__ void hist_k(const int* __restrict__ r0, const int* __restrict__ r1,
                       const int* __restrict__ r2, const int* __restrict__ r3,
                       int* __restrict__ deg)
{
    for (int i = blockIdx.x * 256 + threadIdx.x; i < 4 * EDG; i += HISTB2 * 256) {
        int rel = i / EDG;
        int e   = i - rel * EDG;
        const int* row = (rel == 0) ? r0 : (rel == 1) ? r1 : (rel == 2) ? r2 : r3;
        atomicAdd(&deg[rel * NROW + row[e]], 1);
    }
}

// ================= K3: exclusive scan (verbatim R8) =======================
__global__ void __launch_bounds__(1024) exscan4(const int* __restrict__ degbase,
                                                int* __restrict__ basebase,
                                                int* __restrict__ curbase)
{
    const int* deg = degbase + blockIdx.x * NROW;
    int* base = basebase + blockIdx.x * (NROW + 1);
    int* cur  = curbase  + blockIdx.x * NROW;

    __shared__ int wsum[32];
    __shared__ int carry;
    int tid = threadIdx.x, lane = tid & 31, wid = tid >> 5;
    if (tid == 0) carry = 0;
    __syncthreads();

    for (int start = 0; start < NROW; start += 1024) {
        int i = start + tid;
        int v = (i < NROW) ? deg[i] : 0;
        int x = v;
        #pragma unroll
        for (int off = 1; off < 32; off <<= 1) {
            int t = __shfl_up_sync(0xffffffffu, x, off);
            if (lane >= off) x += t;
        }
        if (lane == 31) wsum[wid] = x;
        __syncthreads();
        if (wid == 0) {
            int s = wsum[lane];
            #pragma unroll
            for (int off = 1; off < 32; off <<= 1) {
                int t = __shfl_up_sync(0xffffffffu, s, off);
                if (lane >= off) s += t;
            }
            wsum[lane] = s;
        }
        __syncthreads();
        int incl = x + (wid ? wsum[wid - 1] : 0) + carry;
        if (i < NROW) { base[i] = incl - v; cur[i] = incl - v; }
        __syncthreads();
        if (tid == 0) carry += wsum[31];
        __syncthreads();
    }
    if (threadIdx.x == 0) base[NROW] = carry;
}

// ================= K4: scatter (4 rel) || proj GEMMs (4) ==================
// scatter blocks first in grid order (latency-bound, start early), gemm after.
#define SCAT_T (4 * SCB)       // 6252
#define GEMMB  (4 * GB)        // 1564
__global__ void __launch_bounds__(256, 2) scatter_proj(
    const int* __restrict__ r0, const int* __restrict__ c0, const float* __restrict__ v0,
    const int* __restrict__ r1, const int* __restrict__ c1, const float* __restrict__ v1,
    const int* __restrict__ r2, const int* __restrict__ c2, const float* __restrict__ v2,
    const int* __restrict__ r3, const int* __restrict__ c3, const float* __restrict__ v3,
    int* __restrict__ curbase, int2* __restrict__ epackbase,
    const __half* __restrict__ xh, const __half* __restrict__ Wh,
    __half* __restrict__ fth)
{
    int bid = blockIdx.x;
    if (bid < SCAT_T) {
        int rel = bid / SCB;
        int i = (bid - rel * SCB) * 256 + threadIdx.x;
        if (i >= EHALF) return;
        const int* row; const int* col; const float* val;
        switch (rel) {
            case 0: row = r0; col = c0; val = v0; break;
            case 1: row = r1; col = c1; val = v1; break;
            case 2: row = r2; col = c2; val = v2; break;
            default: row = r3; col = c3; val = v3; break;
        }
        int* cur = curbase + rel * NROW;
        int2* ep = epackbase + (size_t)rel * EDG;
        int ra = row[i],         rb = row[i + EHALF];
        int ca = col[i],         cb = col[i + EHALF];
        float va = val[i],       vb = val[i + EHALF];
        int pa = atomicAdd(&cur[ra], 1);
        int pb = atomicAdd(&cur[rb], 1);
        ep[pa] = make_int2(ca, __float_as_int(va));
        ep[pb] = make_int2(cb, __float_as_int(vb));
        return;
    }
    bid -= SCAT_T;
    int y = bid / GB;
    int bx = bid - y * GB;
    // y0: x_b@W_ab, y1: x_c@W_ac, y2: x_a@W_ba, y3: x_a@W_ca
    const __half* A = (y == 0) ? xh + 1ull * NROW * 256
                    : (y == 1) ? xh + 2ull * NROW * 256
                               : xh;
    gemm_f16_body<8, true, false>(A, 256, nullptr, 0,
                                  Wh + (size_t)y * 256 * 128, nullptr,
                                  fth + (size_t)y * NROW * 128, nullptr, bx);
}

// ================= gather primitives (verbatim R8) ========================
__device__ __forceinline__ void edge_accum(float4& acc, float v,
                                           const __half* __restrict__ ft,
                                           int c, int lane)
{
    uint2 u = ((const uint2*)(ft + (size_t)c * 128))[lane];
    float2 l0 = __half22float2(*(__half2*)&u.x);
    float2 l1 = __half22float2(*(__half2*)&u.y);
    acc.x += v * l0.x; acc.y += v * l0.y;
    acc.z += v * l1.x; acc.w += v * l1.y;
}

__device__ __forceinline__ float4 gather_row(
    const int2* __restrict__ ep, const int* __restrict__ base,
    int r, const __half* __restrict__ ft, int lane)
{
    int s = base[r], e = base[r + 1];
    float4 acc = make_float4(0.f, 0.f, 0.f, 0.f);
    int j = s;
    for (; j + 3 < e; j += 4) {
        int2 p0 = ep[j],     p1 = ep[j + 1];
        int2 p2 = ep[j + 2], p3 = ep[j + 3];
        edge_accum(acc, __int_as_float(p0.y), ft, p0.x, lane);
        edge_accum(acc, __int_as_float(p1.y), ft, p1.x, lane);
        edge_accum(acc, __int_as_float(p2.y), ft, p2.x, lane);
        edge_accum(acc, __int_as_float(p3.y), ft, p3.x, lane);
    }
    for (; j < e; j++) {
        int2 p = ep[j];
        edge_accum(acc, __int_as_float(p.y), ft, p.x, lane);
    }
    return acc;
}

__device__ __forceinline__ void store_aggh(__half* __restrict__ dst, int warp,
                                           int lane, float4 a)
{
    __half2 h0 = __floats2half2_rn(a.x, a.y);
    __half2 h1 = __floats2half2_rn(a.z, a.w);
    uint2 u; u.x = *(unsigned*)&h0; u.y = *(unsigned*)&h1;
    ((uint2*)(dst + (size_t)warp * 128))[lane] = u;
}

// ================= K5: gather_all (verbatim R8) ===========================
// y=0: rel0+rel1 gather + attention -> aggh[0] ; y=1: rel2 ; y=2: rel3
__global__ void __launch_bounds__(256) gather_all(
    const int2* __restrict__ epack, const int* __restrict__ basebase,
    const __half* __restrict__ fth, const __half* __restrict__ xh,
    const float* __restrict__ uv, __half* __restrict__ aggh)
{
    int warp = (blockIdx.x * blockDim.x + threadIdx.x) >> 5;
    int lane = threadIdx.x & 31;
    if (warp >= NROW) return;

    if (blockIdx.y != 0) {
        int rel = 1 + blockIdx.y;    // 2 or 3
        float4 a = gather_row(epack + (size_t)rel * EDG,
                              basebase + rel * (NROW + 1),
                              warp, fth + (size_t)rel * NROW * 128, lane);
        store_aggh(aggh + (size_t)blockIdx.y * NROW * 128, warp, lane, a);
        return;
    }

    float4 b = gather_row(epack, basebase, warp, fth, lane);
    float4 c = gather_row(epack + EDG, basebase + (NROW + 1), warp,
                          fth + (size_t)NROW * 128, lane);

    float4 u4 = ((const float4*)uv)[lane];
    const __half2* xrow = (const __half2*)(xh + (size_t)warp * 256);
    float4 w0 = ((const float4*)(uv + 256))[lane * 2];
    float4 w1 = ((const float4*)(uv + 256))[lane * 2 + 1];
    float2 q0 = __half22float2(xrow[lane * 4 + 0]);
    float2 q1 = __half22float2(xrow[lane * 4 + 1]);
    float2 q2 = __half22float2(xrow[lane * 4 + 2]);
    float2 q3 = __half22float2(xrow[lane * 4 + 3]);

    float db = b.x * u4.x + b.y * u4.y + b.z * u4.z + b.w * u4.w;
    float dc = c.x * u4.x + c.y * u4.y + c.z * u4.z + c.w * u4.w;
    float ds = q0.x * w0.x + q0.y * w0.y + q1.x * w0.z + q1.y * w0.w
             + q2.x * w1.x + q2.y * w1.y + q3.x * w1.z + q3.y * w1.w;

    #pragma unroll
    for (int o = 16; o; o >>= 1) {
        db += __shfl_xor_sync(0xffffffffu, db, o);
        dc += __shfl_xor_sync(0xffffffffu, dc, o);
        ds += __shfl_xor_sync(0xffffffffu, ds, o);
    }

    float eb = db + ds;
    float ec = dc + ds;
    eb = (eb > 0.f) ? eb : expm1f(eb);
    ec = (ec > 0.f) ? ec : expm1f(ec);
    float m  = fmaxf(eb, ec);
    float wb = expf(eb - m);
    float wc = expf(ec - m);
    float ab = wb / (wb + wc);
    float ac = 1.f - ab;

    float4 o4;
    o4.x = ab * b.x + ac * c.x;
    o4.y = ab * b.y + ac * c.y;
    o4.z = ab * b.z + ac * c.z;
    o4.w = ab * b.w + ac * c.w;
    store_aggh(aggh, warp, lane, o4);
}

// ================= K6: output GEMMs (3 types, one launch) =================
__global__ void __launch_bounds__(256, 2) gemm_out_f16(
    const __half* __restrict__ aggh, const __half* __restrict__ xh,
    const __half* __restrict__ Wcomb,
    const float* __restrict__ ba, const float* __restrict__ bb,
    const float* __restrict__ bc, float* __restrict__ outbase)
{
    gemm_out_body(blockIdx.y, blockIdx.x, aggh, xh, Wcomb, ba, bb, bc, outbase);
}

// ================= launcher ===============================================
extern "C" void kernel_launch(void* const* d_in, const int* in_sizes, int n_in,
                              void* d_out, int out_size)
{
    const float* x_a       = (const float*)d_in[0];
    const float* x_b       = (const float*)d_in[1];
    const float* x_c       = (const float*)d_in[2];
    const int*   row_ab    = (const int*)d_in[3];
    const int*   col_ab    = (const int*)d_in[4];
    const float* val_ab    = (const float*)d_in[5];
    const int*   row_ac    = (const int*)d_in[6];
    const int*   col_ac    = (const int*)d_in[7];
    const float* val_ac    = (const float*)d_in[8];
    const int*   row_ba    = (const int*)d_in[9];
    const int*   col_ba    = (const int*)d_in[10];
    const float* val_ba    = (const float*)d_in[11];
    const int*   row_ca    = (const int*)d_in[12];
    const int*   col_ca    = (const int*)d_in[13];
    const float* val_ca    = (const float*)d_in[14];
    const float* w_self_a  = (const float*)d_in[15];
    const float* w_self_b  = (const float*)d_in[16];
    const float* w_self_c  = (const float*)d_in[17];
    const float* W_ab      = (const float*)d_in[18];
    const float* W_ac      = (const float*)d_in[19];
    const float* W_ba      = (const float*)d_in[20];
    const float* W_ca      = (const float*)d_in[21];
    const float* bias_a    = (const float*)d_in[22];
    const float* bias_b    = (const float*)d_in[23];
    const float* bias_c    = (const float*)d_in[24];
    const float* w_cat_a   = (const float*)d_in[25];
    const float* w_cat_b   = (const float*)d_in[26];
    const float* w_cat_c   = (const float*)d_in[27];
    const float* w_query_a = (const float*)d_in[28];
    const float* w_keys_a  = (const float*)d_in[29];
    const float* w_att_a   = (const float*)d_in[30];

    float* scratch = nullptr;
    cudaGetSymbolAddress((void**)&scratch, g_scratch);

    __half*   aggh    = (__half*)(scratch + OFF_AGGH);
    __half*   fth     = (__half*)(scratch + OFF_FTH);
    __half*   xh      = (__half*)(scratch + OFF_XH);
    __half*   Wh      = (__half*)(scratch + OFF_WH);
    __half*   Wcomb   = (__half*)(scratch + OFF_WCOMB);
    float*    uv      = scratch + OFF_UV;
    int*      deg     = (int*)(scratch + OFF_DEG);
    int*      base    = (int*)(scratch + OFF_BASE);
    int*      cur     = (int*)(scratch + OFF_CUR);
    int2*     epack   = (int2*)(scratch + OFF_EPACK);

    float* out = (float*)d_out;

    const int PREPB = CONVB + WHB + WC1B + FOLDB + UVB + ZEROB;

    // K1: prep (conversions, weight folds, uv/wv, zero deg)
    mega_prep<<<PREPB, 256>>>(x_a, x_b, x_c, (uint2*)xh,
                              W_ab, W_ac, W_ba, W_ca, Wh,
                              w_cat_a, w_cat_b, w_cat_c,
                              w_self_a, w_self_b, w_self_c, Wcomb,
                              w_query_a, w_keys_a, w_att_a, uv, deg);

    // K2: degree histogram
    hist_k<<<HISTB2, 256>>>(row_ab, row_ac, row_ba, row_ca, deg);

    // K3: exclusive scan per relation
    exscan4<<<4, 1024>>>(deg, base, cur);

    // K4: scatter (all 4 relations)  ||  4 projection GEMMs
    scatter_proj<<<SCAT_T + GEMMB, 256>>>(
        row_ab, col_ab, val_ab, row_ac, col_ac, val_ac,
        row_ba, col_ba, val_ba, row_ca, col_ca, val_ca,
        cur, epack, xh, Wh, fth);

    // K5: gather + attention (R8 schedule)
    gather_all<<<dim3(GWB, 3), 256>>>(epack, base, fth, xh, uv, aggh);

    // K6: output GEMMs
    gemm_out_f16<<<dim3(GB, 3), 256>>>(aggh, xh, Wcomb,
                                       bias_a, bias_b, bias_c, out);
}

// round 17
// speedup vs baseline: 1.2081x; 1.0055x over previous
#include <cuda_runtime.h>
#include <cuda_fp16.h>
#include <cstdint>
#include <cstddef>

// ---------------- problem constants ----------------
#define NA 50000
#define NROW 50000
#define EDG 800000
#define EQUAD (EDG / 4)
#define SZ (50000 * 128)        // floats per [N,128] fp32-equivalent slot
#define XQ4 3200000             // float4 count per x array (50000*256/4)

#define GB 391                  // gemm blocks per matrix (128-row tiles)
#define GWB 6250                // gather blocks (8 rows/block)
#define SCB4 782                // scatter blocks per relation (4 edges/thread)

// scratch layout (float units):
#define OFF_AGGH   0ull                           // 3 x [N,128] fp16 (1.5 slots)
#define OFF_FTH    (2ull * SZ)                    // 4 x [N,128] fp16 (2 slots)
#define OFF_XH     (4ull * SZ)                    // 3 x [N,256] fp16 (3 slots)
#define W_OFF      (7ull * SZ)
#define OFF_WH     (W_OFF)                        // 4*256*128 halves = 65536 floats
#define OFF_WCOMB  (OFF_WH + 65536)               // 3*384*128 halves = 73728 floats
#define OFF_UV     (OFF_WCOMB + 73728)            // 512 floats
#define OFF_DEG    (OFF_UV   + 512)
#define OFF_BASE   (OFF_DEG  + 4*50000)
#define OFF_CUR    (OFF_BASE + 4*50004)
#define OFF_EPACK  (((OFF_CUR + 4*50000) + 3) & ~3ull)   // 16B-aligned
#define SCRATCH_TOTAL (OFF_EPACK + 4ull*EDG*2)

__device__ __align__(256) float g_scratch[SCRATCH_TOTAL];

// ---------------- helpers ----------------
__device__ __forceinline__ void ldsm4(unsigned &r0, unsigned &r1, unsigned &r2,
                                      unsigned &r3, unsigned addr) {
    asm volatile("ldmatrix.sync.aligned.m8n8.x4.shared.b16 {%0,%1,%2,%3}, [%4];"
                 : "=r"(r0), "=r"(r1), "=r"(r2), "=r"(r3) : "r"(addr));
}

__device__ __forceinline__ void ldsm4t(unsigned &r0, unsigned &r1, unsigned &r2,
                                       unsigned &r3, unsigned addr) {
    asm volatile("ldmatrix.sync.aligned.m8n8.x4.trans.shared.b16 {%0,%1,%2,%3}, [%4];"
                 : "=r"(r0), "=r"(r1), "=r"(r2), "=r"(r3) : "r"(addr));
}

__device__ __forceinline__ void mma_f16(float c[4], const unsigned a[4],
                                        unsigned b0, unsigned b1) {
    asm volatile(
        "mma.sync.aligned.m16n8k16.row.col.f32.f16.f16.f32 "
        "{%0,%1,%2,%3}, {%4,%5,%6,%7}, {%8,%9}, {%0,%1,%2,%3};"
        : "+f"(c[0]), "+f"(c[1]), "+f"(c[2]), "+f"(c[3])
        : "r"(a[0]), "r"(a[1]), "r"(a[2]), "r"(a[3]), "r"(b0), "r"(b1));
}

__device__ __forceinline__ void cpasync16(void* sdst, const void* gsrc, int nbytes) {
    unsigned s = (unsigned)__cvta_generic_to_shared(sdst);
    asm volatile("cp.async.cg.shared.global [%0], [%1], 16, %2;\n"
                 :: "r"(s), "l"(gsrc), "r"(nbytes));
}

// ================= fp16 GEMM body (K-tiles of 32) =========================
template<int NKT, bool HOUT, bool SPLIT>
__device__ __forceinline__ void gemm_f16_body(
    const __half* __restrict__ A0, int lda0,
    const __half* __restrict__ A1, int lda1,
    const __half* __restrict__ B,                     // [K][128] row-major
    const float* __restrict__ bias,
    __half* __restrict__ Yh, float* __restrict__ Yf, int bx)
{
    __shared__ __half As[2][128][40];    // 32 k + 8 pad
    __shared__ __half Bs[2][32][136];    // [k][n], 128 n + 8 pad

    const int tid  = threadIdx.x;
    const int lane = tid & 31;
    const int w    = tid >> 5;
    const int bm   = bx * 128;

    const int wm = (w >> 2) * 64;
    const int wn = (w & 3) * 32;

    float acc[4][4][4];
    #pragma unroll
    for (int i = 0; i < 4; i++)
        #pragma unroll
        for (int j = 0; j < 4; j++)
            #pragma unroll
            for (int c = 0; c < 4; c++) acc[i][j][c] = 0.f;

    auto stage = [&](int buf, int k0) {
        const __half* asrc; int ld, col;
        if (SPLIT && k0 >= 128) { asrc = A1; ld = lda1; col = k0 - 128; }
        else                    { asrc = A0; ld = lda0; col = k0; }
        #pragma unroll
        for (int i = 0; i < 2; i++) {
            int slot = tid + i * 256;
            int r = slot >> 2, c = (slot & 3) * 8;
            int grow = bm + r;
            const __half* src = asrc + (size_t)(grow < NA ? grow : 0) * ld + col + c;
            cpasync16(&As[buf][r][c], src, grow < NA ? 16 : 0);
        }
        #pragma unroll
        for (int i = 0; i < 2; i++) {
            int slot = tid + i * 256;
            int r = slot >> 4, c = (slot & 15) * 8;
            cpasync16(&Bs[buf][r][c], B + (size_t)(k0 + r) * 128 + c, 16);
        }
        asm volatile("cp.async.commit_group;\n" ::);
    };

    stage(0, 0);

    for (int kt = 0; kt < NKT; kt++) {
        if (kt + 1 < NKT) {
            stage((kt + 1) & 1, (kt + 1) * 32);
            asm volatile("cp.async.wait_group 1;\n" ::);
        } else {
            asm volatile("cp.async.wait_group 0;\n" ::);
        }
        __syncthreads();

        const int buf = kt & 1;
        #pragma unroll
        for (int ks = 0; ks < 2; ks++) {
            const int k16 = ks * 16;
            unsigned a[4][4], b0[4], b1[4];
            #pragma unroll
            for (int mt = 0; mt < 4; mt++) {
                unsigned addr = (unsigned)__cvta_generic_to_shared(
                    &As[buf][wm + mt * 16 + (lane & 15)][k16 + (lane >> 4) * 8]);
                ldsm4(a[mt][0], a[mt][1], a[mt][2], a[mt][3], addr);
            }
            #pragma unroll
            for (int np = 0; np < 2; np++) {
                unsigned addr = (unsigned)__cvta_generic_to_shared(
                    &Bs[buf][k16 + (lane & 15)][wn + np * 16 + (lane >> 4) * 8]);
                ldsm4t(b0[np * 2], b1[np * 2], b0[np * 2 + 1], b1[np * 2 + 1], addr);
            }
            #pragma unroll
            for (int mt = 0; mt < 4; mt++)
                #pragma unroll
                for (int nt = 0; nt < 4; nt++)
                    mma_f16(acc[mt][nt], a[mt], b0[nt], b1[nt]);
        }
        __syncthreads();
    }

    const int g = lane >> 2, tg = lane & 3;
    #pragma unroll
    for (int nt = 0; nt < 4; nt++) {
        int cc = wn + nt * 8 + tg * 2;
        float bx0 = HOUT ? 0.f : bias[cc];
        float bx1 = HOUT ? 0.f : bias[cc + 1];
        #pragma unroll
        for (int mt = 0; mt < 4; mt++) {
            int r = bm + wm + mt * 16 + g;
            if (r < NA) {
                if (HOUT)
                    *(__half2*)(Yh + (size_t)r * 128 + cc) =
                        __floats2half2_rn(acc[mt][nt][0], acc[mt][nt][1]);
                else
                    *(float2*)(Yf + (size_t)r * 128 + cc) =
                        make_float2(acc[mt][nt][0] + bx0, acc[mt][nt][1] + bx1);
            }
            if (r + 8 < NA) {
                if (HOUT)
                    *(__half2*)(Yh + (size_t)(r + 8) * 128 + cc) =
                        __floats2half2_rn(acc[mt][nt][2], acc[mt][nt][3]);
                else
                    *(float2*)(Yf + (size_t)(r + 8) * 128 + cc) =
                        make_float2(acc[mt][nt][2] + bx0, acc[mt][nt][3] + bx1);
            }
        }
    }
}

// ---- output GEMM body ----
__device__ __forceinline__ void gemm_out_body(
    int y, int bx,
    const __half* __restrict__ aggh, const __half* __restrict__ xh,
    const __half* __restrict__ Wcomb,
    const float* __restrict__ ba, const float* __restrict__ bb,
    const float* __restrict__ bc, float* __restrict__ outbase)
{
    const float* bias = (y == 0) ? ba : (y == 1) ? bb : bc;
    gemm_f16_body<12, false, true>(
        aggh + (size_t)y * NROW * 128, 128,
        xh   + (size_t)y * NROW * 256, 256,
        Wcomb + (size_t)y * 384 * 128,
        bias, nullptr, outbase + (size_t)y * NROW * 128, bx);
}

// ================= K1: mega prep (verbatim R15) ===========================
#define CONVB 2048
#define WHB   512
#define WC1B  192
#define FOLDB 384
#define UVB   1
#define ZEROB 782
__global__ void mega_prep(
    const float* __restrict__ xa, const float* __restrict__ xb,
    const float* __restrict__ xc, uint2* __restrict__ xh_u2,
    const float* __restrict__ Wab, const float* __restrict__ Wac,
    const float* __restrict__ Wba, const float* __restrict__ Wca,
    __half* __restrict__ Wh,
    const float* __restrict__ wca_, const float* __restrict__ wcb_,
    const float* __restrict__ wcc_,
    const float* __restrict__ wsa, const float* __restrict__ wsb,
    const float* __restrict__ wsc, __half* __restrict__ Wcomb,
    const float* __restrict__ wq, const float* __restrict__ wk,
    const float* __restrict__ watt, float* __restrict__ uv,
    int* __restrict__ deg)
{
    int bid = blockIdx.x;
    int tid = threadIdx.x;

    if (bid < CONVB) {
        for (int i = bid * 256 + tid; i < 3 * XQ4; i += CONVB * 256) {
            int arr = i / XQ4;
            int off = i - arr * XQ4;
            const float* src = (arr == 0) ? xa : (arr == 1) ? xb : xc;
            float4 v = ((const float4*)src)[off];
            __half2 h0 = __floats2half2_rn(v.x, v.y);
            __half2 h1 = __floats2half2_rn(v.z, v.w);
            uint2 u;
            u.x = *(unsigned*)&h0;
            u.y = *(unsigned*)&h1;
            xh_u2[(size_t)arr * XQ4 + off] = u;
        }
        return;
    }
    bid -= CONVB;
    if (bid < WHB) {
        int rel = bid >> 7, blk = bid & 127;
        const float* W = (rel == 0) ? Wab : (rel == 1) ? Wac : (rel == 2) ? Wba : Wca;
        int idx = blk * 256 + tid;
        Wh[(size_t)rel * 32768 + idx] = __float2half(W[idx]);
        return;
    }
    bid -= WHB;
    if (bid < WC1B) {
        int m = bid / 64, blk = bid - m * 64;
        const float* wc = (m == 0) ? wca_ : (m == 1) ? wcb_ : wcc_;
        int idx = blk * 256 + tid;   // 0..16383
        Wcomb[(size_t)m * 49152 + idx] = __float2half(wc[idx]);
        return;
    }
    bid -= WC1B;
    if (bid < FOLDB) {
        int m = bid >> 7, blk = bid & 127;
        const float* ws = (m == 0) ? wsa : (m == 1) ? wsb : wsc;
        const float* wc = ((m == 0) ? wca_ : (m == 1) ? wcb_ : wcc_) + 128 * 128;
        int idx = blk * 256 + tid;   // 0..32767
        int k = idx >> 7, n = idx & 127;
        float s = 0.f;
        #pragma unroll 8
        for (int j = 0; j < 128; j++) s += ws[k * 128 + j] * wc[j * 128 + n];
        Wcomb[(size_t)m * 49152 + (128 + k) * 128 + n] = __float2half(s);
        return;
    }
    bid -= FOLDB;
    if (bid < UVB) {
        if (tid < 128) {
            float s = 0.f;
            #pragma unroll
            for (int j = 0; j < 64; j++) s += wk[tid * 64 + j] * watt[j];
            uv[tid] = s;
        } else {
            int i = tid - 128;
            float s = 0.f;
            #pragma unroll
            for (int j = 0; j < 64; j++) s += wq[i * 64 + j] * watt[64 + j];
            uv[128 + i] = s;
        }
        __syncthreads();
        {
            const float* v = uv + 128;
            float s = 0.f;
            #pragma unroll 8
            for (int j = 0; j < 128; j++) s += wsa[tid * 128 + j] * v[j];
            uv[256 + tid] = s;
        }
        return;
    }
    bid -= UVB;
    {
        int i = bid * 256 + tid;
        if (i < 4 * NROW) deg[i] = 0;
    }
}

// ================= K2: standalone degree histogram ========================
#define HISTB2 4096
__global__ void hist_k(const int* __restrict__ r0, const int* __restrict__ r1,
                       const int* __restrict__ r2, const int* __restrict__ r3,
                       int* __restrict__ deg)
{
    for (int i = blockIdx.x * 256 + threadIdx.x; i < 4 * EDG; i += HISTB2 * 256) {
        int rel = i / EDG;
        int e   = i - rel * EDG;
        const int* row = (rel == 0) ? r0 : (rel == 1) ? r1 : (rel == 2) ? r2 : r3;
        atomicAdd(&deg[rel * NROW + row[e]], 1);
    }
}

// ================= K3: exclusive scan (verbatim R15) ======================
__global__ void __launch_bounds__(1024) exscan4(const int* __restrict__ degbase,
                                                int* __restrict__ basebase,
                                                int* __restrict__ curbase)
{
    const int* deg = degbase + blockIdx.x * NROW;
    int* base = basebase + blockIdx.x * (NROW + 1);
    int* cur  = curbase  + blockIdx.x * NROW;

    __shared__ int wsum[32];
    __shared__ int carry;
    int tid = threadIdx.x, lane = tid & 31, wid = tid >> 5;
    if (tid == 0) carry = 0;
    __syncthreads();

    for (int start = 0; start < NROW; start += 1024) {
        int i = start + tid;
        int v = (i < NROW) ? deg[i] : 0;
        int x = v;
        #pragma unroll
        for (int off = 1; off < 32; off <<= 1) {
            int t = __shfl_up_sync(0xffffffffu, x, off);
            if (lane >= off) x += t;
        }
        if (lane == 31) wsum[wid] = x;
        __syncthreads();
        if (wid == 0) {
            int s = wsum[lane];
            #pragma unroll
            for (int off = 1; off < 32; off <<= 1) {
                int t = __shfl_up_sync(0xffffffffu, s, off);
                if (lane >= off) s += t;
            }
            wsum[lane] = s;
        }
        __syncthreads();
        int incl = x + (wid ? wsum[wid - 1] : 0) + carry;
        if (i < NROW) { base[i] = incl - v; cur[i] = incl - v; }
        __syncthreads();
        if (tid == 0) carry += wsum[31];
        __syncthreads();
    }
    if (threadIdx.x == 0) base[NROW] = carry;
}

// ================= K4: scatter (4 rel, 4 edges/thread) || proj GEMMs ======
// scatter blocks first in grid order; 4 independent chains/thread to
// compensate for the occ-2 limit imposed by the gemm path's 128 regs.
#define SCAT_T (4 * SCB4)      // 3128
#define GEMMB  (4 * GB)        // 1564
__global__ void __launch_bounds__(256, 2) scatter_proj(
    const int* __restrict__ r0, const int* __restrict__ c0, const float* __restrict__ v0,
    const int* __restrict__ r1, const int* __restrict__ c1, const float* __restrict__ v1,
    const int* __restrict__ r2, const int* __restrict__ c2, const float* __restrict__ v2,
    const int* __restrict__ r3, const int* __restrict__ c3, const float* __restrict__ v3,
    int* __restrict__ curbase, int2* __restrict__ epackbase,
    const __half* __restrict__ xh, const __half* __restrict__ Wh,
    __half* __restrict__ fth)
{
    int bid = blockIdx.x;
    if (bid < SCAT_T) {
        int rel = bid / SCB4;
        int i = (bid - rel * SCB4) * 256 + threadIdx.x;
        if (i >= EQUAD) return;
        const int* row; const int* col; const float* val;
        switch (rel) {
            case 0: row = r0; col = c0; val = v0; break;
            case 1: row = r1; col = c1; val = v1; break;
            case 2: row = r2; col = c2; val = v2; break;
            default: row = r3; col = c3; val = v3; break;
        }
        int* cur = curbase + rel * NROW;
        int2* ep = epackbase + (size_t)rel * EDG;
        int i0 = i, i1 = i + EQUAD, i2 = i + 2 * EQUAD, i3 = i + 3 * EQUAD;
        int   ra = row[i0], rb = row[i1], rc = row[i2], rd = row[i3];
        int   ca = col[i0], cb = col[i1], cc = col[i2], cd = col[i3];
        float va = val[i0], vb = val[i1], vc = val[i2], vd = val[i3];
        int pa = atomicAdd(&cur[ra], 1);
        int pb = atomicAdd(&cur[rb], 1);
        int pc = atomicAdd(&cur[rc], 1);
        int pd = atomicAdd(&cur[rd], 1);
        ep[pa] = make_int2(ca, __float_as_int(va));
        ep[pb] = make_int2(cb, __float_as_int(vb));
        ep[pc] = make_int2(cc, __float_as_int(vc));
        ep[pd] = make_int2(cd, __float_as_int(vd));
        return;
    }
    bid -= SCAT_T;
    int y = bid / GB;
    int bx = bid - y * GB;
    // y0: x_b@W_ab, y1: x_c@W_ac, y2: x_a@W_ba, y3: x_a@W_ca
    const __half* A = (y == 0) ? xh + 1ull * NROW * 256
                    : (y == 1) ? xh + 2ull * NROW * 256
                               : xh;
    gemm_f16_body<8, true, false>(A, 256, nullptr, 0,
                                  Wh + (size_t)y * 256 * 128, nullptr,
                                  fth + (size_t)y * NROW * 128, nullptr, bx);
}

// ================= gather primitives (verbatim R15) =======================
__device__ __forceinline__ void edge_accum(float4& acc, float v,
                                           const __half* __restrict__ ft,
                                           int c, int lane)
{
    uint2 u = ((const uint2*)(ft + (size_t)c * 128))[lane];
    float2 l0 = __half22float2(*(__half2*)&u.x);
    float2 l1 = __half22float2(*(__half2*)&u.y);
    acc.x += v * l0.x; acc.y += v * l0.y;
    acc.z += v * l1.x; acc.w += v * l1.y;
}

__device__ __forceinline__ float4 gather_row(
    const int2* __restrict__ ep, const int* __restrict__ base,
    int r, const __half* __restrict__ ft, int lane)
{
    int s = base[r], e = base[r + 1];
    float4 acc = make_float4(0.f, 0.f, 0.f, 0.f);
    int j = s;
    for (; j + 3 < e; j += 4) {
        int2 p0 = ep[j],     p1 = ep[j + 1];
        int2 p2 = ep[j + 2], p3 = ep[j + 3];
        edge_accum(acc, __int_as_float(p0.y), ft, p0.x, lane);
        edge_accum(acc, __int_as_float(p1.y), ft, p1.x, lane);
        edge_accum(acc, __int_as_float(p2.y), ft, p2.x, lane);
        edge_accum(acc, __int_as_float(p3.y), ft, p3.x, lane);
    }
    for (; j < e; j++) {
        int2 p = ep[j];
        edge_accum(acc, __int_as_float(p.y), ft, p.x, lane);
    }
    return acc;
}

__device__ __forceinline__ void store_aggh(__half* __restrict__ dst, int warp,
                                           int lane, float4 a)
{
    __half2 h0 = __floats2half2_rn(a.x, a.y);
    __half2 h1 = __floats2half2_rn(a.z, a.w);
    uint2 u; u.x = *(unsigned*)&h0; u.y = *(unsigned*)&h1;
    ((uint2*)(dst + (size_t)warp * 128))[lane] = u;
}

// ================= K5: gather_all (verbatim R15) ==========================
// y=0: rel0+rel1 gather + attention -> aggh[0] ; y=1: rel2 ; y=2: rel3
__global__ void __launch_bounds__(256) gather_all(
    const int2* __restrict__ epack, const int* __restrict__ basebase,
    const __half* __restrict__ fth, const __half* __restrict__ xh,
    const float* __restrict__ uv, __half* __restrict__ aggh)
{
    int warp = (blockIdx.x * blockDim.x + threadIdx.x) >> 5;
    int lane = threadIdx.x & 31;
    if (warp >= NROW) return;

    if (blockIdx.y != 0) {
        int rel = 1 + blockIdx.y;    // 2 or 3
        float4 a = gather_row(epack + (size_t)rel * EDG,
                              basebase + rel * (NROW + 1),
                              warp, fth + (size_t)rel * NROW * 128, lane);
        store_aggh(aggh + (size_t)blockIdx.y * NROW * 128, warp, lane, a);
        return;
    }

    float4 b = gather_row(epack, basebase, warp, fth, lane);
    float4 c = gather_row(epack + EDG, basebase + (NROW + 1), warp,
                          fth + (size_t)NROW * 128, lane);

    float4 u4 = ((const float4*)uv)[lane];
    const __half2* xrow = (const __half2*)(xh + (size_t)warp * 256);
    float4 w0 = ((const float4*)(uv + 256))[lane * 2];
    float4 w1 = ((const float4*)(uv + 256))[lane * 2 + 1];
    float2 q0 = __half22float2(xrow[lane * 4 + 0]);
    float2 q1 = __half22float2(xrow[lane * 4 + 1]);
    float2 q2 = __half22float2(xrow[lane * 4 + 2]);
    float2 q3 = __half22float2(xrow[lane * 4 + 3]);

    float db = b.x * u4.x + b.y * u4.y + b.z * u4.z + b.w * u4.w;
    float dc = c.x * u4.x + c.y * u4.y + c.z * u4.z + c.w * u4.w;
    float ds = q0.x * w0.x + q0.y * w0.y + q1.x * w0.z + q1.y * w0.w
             + q2.x * w1.x + q2.y * w1.y + q3.x * w1.z + q3.y * w1.w;

    #pragma unroll
    for (int o = 16; o; o >>= 1) {
        db += __shfl_xor_sync(0xffffffffu, db, o);
        dc += __shfl_xor_sync(0xffffffffu, dc, o);
        ds += __shfl_xor_sync(0xffffffffu, ds, o);
    }

    float eb = db + ds;
    float ec = dc + ds;
    eb = (eb > 0.f) ? eb : expm1f(eb);
    ec = (ec > 0.f) ? ec : expm1f(ec);
    float m  = fmaxf(eb, ec);
    float wb = expf(eb - m);
    float wc = expf(ec - m);
    float ab = wb / (wb + wc);
    float ac = 1.f - ab;

    float4 o4;
    o4.x = ab * b.x + ac * c.x;
    o4.y = ab * b.y + ac * c.y;
    o4.z = ab * b.z + ac * c.z;
    o4.w = ab * b.w + ac * c.w;
    store_aggh(aggh, warp, lane, o4);
}

// ================= K6: output GEMMs (3 types, one launch) =================
__global__ void __launch_bounds__(256, 2) gemm_out_f16(
    const __half* __restrict__ aggh, const __half* __restrict__ xh,
    const __half* __restrict__ Wcomb,
    const float* __restrict__ ba, const float* __restrict__ bb,
    const float* __restrict__ bc, float* __restrict__ outbase)
{
    gemm_out_body(blockIdx.y, blockIdx.x, aggh, xh, Wcomb, ba, bb, bc, outbase);
}

// ================= launcher ===============================================
extern "C" void kernel_launch(void* const* d_in, const int* in_sizes, int n_in,
                              void* d_out, int out_size)
{
    const float* x_a       = (const float*)d_in[0];
    const float* x_b       = (const float*)d_in[1];
    const float* x_c       = (const float*)d_in[2];
    const int*   row_ab    = (const int*)d_in[3];
    const int*   col_ab    = (const int*)d_in[4];
    const float* val_ab    = (const float*)d_in[5];
    const int*   row_ac    = (const int*)d_in[6];
    const int*   col_ac    = (const int*)d_in[7];
    const float* val_ac    = (const float*)d_in[8];
    const int*   row_ba    = (const int*)d_in[9];
    const int*   col_ba    = (const int*)d_in[10];
    const float* val_ba    = (const float*)d_in[11];
    const int*   row_ca    = (const int*)d_in[12];
    const int*   col_ca    = (const int*)d_in[13];
    const float* val_ca    = (const float*)d_in[14];
    const float* w_self_a  = (const float*)d_in[15];
    const float* w_self_b  = (const float*)d_in[16];
    const float* w_self_c  = (const float*)d_in[17];
    const float* W_ab      = (const float*)d_in[18];
    const float* W_ac      = (const float*)d_in[19];
    const float* W_ba      = (const float*)d_in[20];
    const float* W_ca      = (const float*)d_in[21];
    const float* bias_a    = (const float*)d_in[22];
    const float* bias_b    = (const float*)d_in[23];
    const float* bias_c    = (const float*)d_in[24];
    const float* w_cat_a   = (const float*)d_in[25];
    const float* w_cat_b   = (const float*)d_in[26];
    const float* w_cat_c   = (const float*)d_in[27];
    const float* w_query_a = (const float*)d_in[28];
    const float* w_keys_a  = (const float*)d_in[29];
    const float* w_att_a   = (const float*)d_in[30];

    float* scratch = nullptr;
    cudaGetSymbolAddress((void**)&scratch, g_scratch);

    __half*   aggh    = (__half*)(scratch + OFF_AGGH);
    __half*   fth     = (__half*)(scratch + OFF_FTH);
    __half*   xh      = (__half*)(scratch + OFF_XH);
    __half*   Wh      = (__half*)(scratch + OFF_WH);
    __half*   Wcomb   = (__half*)(scratch + OFF_WCOMB);
    float*    uv      = scratch + OFF_UV;
    int*      deg     = (int*)(scratch + OFF_DEG);
    int*      base    = (int*)(scratch + OFF_BASE);
    int*      cur     = (int*)(scratch + OFF_CUR);
    int2*     epack   = (int2*)(scratch + OFF_EPACK);

    float* out = (float*)d_out;

    const int PREPB = CONVB + WHB + WC1B + FOLDB + UVB + ZEROB;

    // K1: prep (conversions, weight folds, uv/wv, zero deg)
    mega_prep<<<PREPB, 256>>>(x_a, x_b, x_c, (uint2*)xh,
                              W_ab, W_ac, W_ba, W_ca, Wh,
                              w_cat_a, w_cat_b, w_cat_c,
                              w_self_a, w_self_b, w_self_c, Wcomb,
                              w_query_a, w_keys_a, w_att_a, uv, deg);

    // K2: degree histogram
    hist_k<<<HISTB2, 256>>>(row_ab, row_ac, row_ba, row_ca, deg);

    // K3: exclusive scan per relation
    exscan4<<<4, 1024>>>(deg, base, cur);

    // K4: scatter (all 4 relations, 4 edges/thread)  ||  4 projection GEMMs
    scatter_proj<<<SCAT_T + GEMMB, 256>>>(
        row_ab, col_ab, val_ab, row_ac, col_ac, val_ac,
        row_ba, col_ba, val_ba, row_ca, col_ca, val_ca,
        cur, epack, xh, Wh, fth);

    // K5: gather + attention (R8 schedule)
    gather_all<<<dim3(GWB, 3), 256>>>(epack, base, fth, xh, uv, aggh);

    // K6: output GEMMs
    gemm_out_f16<<<dim3(GB, 3), 256>>>(aggh, xh, Wcomb,
                                       bias_a, bias_b, bias_c, out);
}